// round 5
// baseline (speedup 1.0000x reference)
#include <cuda_runtime.h>
#include <cstddef>
#include <cstdint>

#define N_NODES   100000
#define N_EDGES   3200000
#define N_GRAPHS  64
#define N_CLASSES 10

// ---------------------------------------------------------------------------
// Static device scratch (no allocation allowed)
// ---------------------------------------------------------------------------
__device__ float g_bufA[(size_t)N_NODES * 512];    // 204.8 MB
__device__ float g_bufB[(size_t)N_NODES * 1024];   // 409.6 MB
__device__ float g_wt[1222656];                    // transposed (tf32-rounded) weights
__device__ int   g_in_deg[N_NODES];
__device__ int   g_out_deg[N_NODES];
__device__ float g_in_inv[N_NODES];
__device__ float g_out_inv[N_NODES];
__device__ int   g_row_off[N_NODES + 1];
__device__ int   g_cursor[N_NODES];
__device__ int   g_csr_src[N_EDGES];
__device__ int   g_blocksum[128];
__device__ int   g_blockoff[128];
__device__ float g_pool[N_GRAPHS * 32];
__device__ float g_cnt[N_GRAPHS];

// ---------------------------------------------------------------------------
// Family-portable helpers (sm_80-era: cp.async + mma.sync tf32)
// ---------------------------------------------------------------------------
__device__ __forceinline__ void cp16(uint32_t dst, const void* src, bool valid) {
    asm volatile("cp.async.cg.shared.global [%0], [%1], 16, %2;"
                 :: "r"(dst), "l"(src), "r"(valid ? 16 : 0));
}
#define CP_COMMIT() asm volatile("cp.async.commit_group;" ::: "memory")
#define CP_WAIT(n)  asm volatile("cp.async.wait_group %0;" :: "n"(n) : "memory")

__device__ __forceinline__ float to_tf32(float x) {
    float y;
    asm("cvt.rna.tf32.f32 %0, %1;" : "=f"(y) : "f"(x));
    return y;
}

__device__ __forceinline__ void mma_tf32(float* d, const uint32_t* a,
                                         uint32_t b0, uint32_t b1) {
    asm volatile(
        "mma.sync.aligned.m16n8k8.row.col.f32.tf32.tf32.f32 "
        "{%0,%1,%2,%3}, {%4,%5,%6,%7}, {%8,%9}, {%0,%1,%2,%3};"
        : "+f"(d[0]), "+f"(d[1]), "+f"(d[2]), "+f"(d[3])
        : "r"(a[0]), "r"(a[1]), "r"(a[2]), "r"(a[3]), "r"(b0), "r"(b1));
}

// ---------------------------------------------------------------------------
// Preprocessing
// ---------------------------------------------------------------------------
__global__ void init_zero_kernel() {
    int i = blockIdx.x * blockDim.x + threadIdx.x;
    if (i < N_NODES) { g_in_deg[i] = 0; g_out_deg[i] = 0; g_cursor[i] = 0; }
    if (i < N_GRAPHS * 32) g_pool[i] = 0.0f;
    if (i < N_GRAPHS) g_cnt[i] = 0.0f;
}

__global__ void degree_kernel(const int* __restrict__ src, const int* __restrict__ dst) {
    int e = blockIdx.x * blockDim.x + threadIdx.x;
    if (e < N_EDGES) {
        atomicAdd(&g_out_deg[src[e]], 1);
        atomicAdd(&g_in_deg[dst[e]], 1);
    }
}

__global__ void inv_kernel() {
    int i = blockIdx.x * blockDim.x + threadIdx.x;
    if (i < N_NODES) {
        g_out_inv[i] = rsqrtf(fmaxf((float)g_out_deg[i], 1.0f));
        g_in_inv[i]  = rsqrtf(fmaxf((float)g_in_deg[i], 1.0f));
    }
}

#define SCAN_BLK 98
__global__ void scan_pass1() {
    __shared__ int temp[1024];
    int tid = threadIdx.x;
    int i = blockIdx.x * 1024 + tid;
    int v = (i < N_NODES) ? g_in_deg[i] : 0;
    temp[tid] = v;
    __syncthreads();
    for (int off = 1; off < 1024; off <<= 1) {
        int t = (tid >= off) ? temp[tid - off] : 0;
        __syncthreads();
        temp[tid] += t;
        __syncthreads();
    }
    if (i < N_NODES) g_row_off[i] = temp[tid] - v;
    if (tid == 1023) g_blocksum[blockIdx.x] = temp[1023];
}

__global__ void scan_pass2() {
    __shared__ int s[SCAN_BLK];
    int tid = threadIdx.x;
    if (tid < SCAN_BLK) s[tid] = g_blocksum[tid];
    __syncthreads();
    if (tid == 0) {
        int acc = 0;
        for (int b = 0; b < SCAN_BLK; b++) { int t = s[b]; s[b] = acc; acc += t; }
        g_row_off[N_NODES] = acc;
    }
    __syncthreads();
    if (tid < SCAN_BLK) g_blockoff[tid] = s[tid];
}

__global__ void scan_pass3() {
    int i = blockIdx.x * 1024 + threadIdx.x;
    if (i < N_NODES) g_row_off[i] += g_blockoff[blockIdx.x];
}

__global__ void bin_kernel(const int* __restrict__ src, const int* __restrict__ dst) {
    int e = blockIdx.x * blockDim.x + threadIdx.x;
    if (e < N_EDGES) {
        int d = dst[e];
        int pos = g_row_off[d] + atomicAdd(&g_cursor[d], 1);
        g_csr_src[pos] = src[e];
    }
}

// W[k][n] -> Wt[n][k], rounded to tf32
__global__ void transpose_kernel(const float* __restrict__ W, float* __restrict__ Wt,
                                 int K, int N) {
    int i = blockIdx.x * blockDim.x + threadIdx.x;
    if (i < K * N) {
        int k = i / N, n = i % N;
        Wt[(size_t)n * K + k] = to_tf32(W[i]);
    }
}

// ---------------------------------------------------------------------------
// SpMM (feature-chunked for L2 residency):
//   Y[n, f] = in_inv[n] * sum_{s in N(n)} out_inv[s] * X[s, f]  (+bias, relu)
// grid.y selects a CW-wide feature chunk; chunks run (approximately)
// sequentially because blockIdx.x varies fastest. Streaming stores keep the
// X working set resident in L2.
// ---------------------------------------------------------------------------
template <int CW, bool EPI, bool CVT>
__global__ void spmm_kernel(const float* __restrict__ X, float* __restrict__ Y,
                            const float* __restrict__ bias, int D) {
    constexpr int NPB = 256 / CW;   // nodes per block
    int node = blockIdx.x * NPB + threadIdx.x / CW;
    if (node >= N_NODES) return;
    int f = (threadIdx.x % CW) + blockIdx.y * CW;

    float acc = 0.0f;
    int s0 = g_row_off[node];
    int s1 = g_row_off[node + 1];
    const float* Xf = X + f;
    for (int j = s0; j < s1; j++) {
        int s = __ldg(&g_csr_src[j]);
        acc += __ldg(&g_out_inv[s]) * __ldg(Xf + (size_t)s * D);
    }
    float v = acc * g_in_inv[node];
    if (EPI) v = fmaxf(v + bias[f], 0.0f);
    if (CVT) v = to_tf32(v);
    __stcs(Y + (size_t)node * D + f, v);
}

// ---------------------------------------------------------------------------
// tf32 mma.sync GEMM: C[M,N] = A[M,K] @ Bt[N,K]^T  (+bias, relu)
// 128 x BN tile, BK=32, 256 thr (warps 4x2), cp.async double-buffered.
// ---------------------------------------------------------------------------
template <int BN, bool EPI>
__global__ void __launch_bounds__(256, 1)
mma_gemm_kernel(const float* __restrict__ A, const float* __restrict__ Bt,
                const float* __restrict__ bias, float* __restrict__ C,
                int M, int K, int N) {
    extern __shared__ float sm[];
    constexpr int LD = 36;
    constexpr int A_FLOATS = 128 * LD;
    constexpr int B_FLOATS = BN * LD;
    constexpr int STAGE = A_FLOATS + B_FLOATS;
    constexpr int WN = BN / 2;
    constexpr int NT = WN / 8;

    int tid = threadIdx.x;
    int lane = tid & 31, w = tid >> 5;
    int wm = w & 3, wn = w >> 2;
    int gid = lane >> 2, tig = lane & 3;
    int block_m = blockIdx.y * 128;
    int block_n = blockIdx.x * BN;

    uint32_t sm_u32 = (uint32_t)__cvta_generic_to_shared(sm);
    const int nChunks = K >> 5;

    auto load_stage = [&](int c, int buf) {
        int k0 = c << 5;
        uint32_t abase = sm_u32 + buf * STAGE * 4;
        uint32_t bbase = abase + A_FLOATS * 4;
#pragma unroll
        for (int t = 0; t < 4; t++) {
            int idx = tid + t * 256;
            int row = idx >> 3, c4 = idx & 7;
            int gm = block_m + row;
            cp16(abase + (row * LD + c4 * 4) * 4,
                 A + (size_t)gm * K + k0 + c4 * 4, gm < M);
        }
#pragma unroll
        for (int t = 0; t < BN * 8 / 256; t++) {
            int idx = tid + t * 256;
            int row = idx >> 3, c4 = idx & 7;
            cp16(bbase + (row * LD + c4 * 4) * 4,
                 Bt + (size_t)(block_n + row) * K + k0 + c4 * 4, true);
        }
        CP_COMMIT();
    };

    float acc[2][NT][4];
#pragma unroll
    for (int mi = 0; mi < 2; mi++)
#pragma unroll
        for (int ni = 0; ni < NT; ni++)
#pragma unroll
            for (int j = 0; j < 4; j++) acc[mi][ni][j] = 0.0f;

    load_stage(0, 0);

    for (int c = 0; c < nChunks; c++) {
        if (c + 1 < nChunks) {
            load_stage(c + 1, (c + 1) & 1);
            CP_WAIT(1);
        } else {
            CP_WAIT(0);
        }
        __syncthreads();

        const float* AsC = sm + (c & 1) * STAGE;
        const float* BsC = AsC + A_FLOATS;

#pragma unroll
        for (int kk = 0; kk < 4; kk++) {
            uint32_t af[2][4];
#pragma unroll
            for (int mi = 0; mi < 2; mi++) {
                int r0 = wm * 32 + mi * 16 + gid;
                af[mi][0] = __float_as_uint(AsC[r0 * LD + kk * 8 + tig]);
                af[mi][1] = __float_as_uint(AsC[(r0 + 8) * LD + kk * 8 + tig]);
                af[mi][2] = __float_as_uint(AsC[r0 * LD + kk * 8 + tig + 4]);
                af[mi][3] = __float_as_uint(AsC[(r0 + 8) * LD + kk * 8 + tig + 4]);
            }
#pragma unroll
            for (int ni = 0; ni < NT; ni++) {
                int br = wn * WN + ni * 8 + gid;
                uint32_t b0 = __float_as_uint(BsC[br * LD + kk * 8 + tig]);
                uint32_t b1 = __float_as_uint(BsC[br * LD + kk * 8 + tig + 4]);
                mma_tf32(acc[0][ni], af[0], b0, b1);
                mma_tf32(acc[1][ni], af[1], b0, b1);
            }
        }
        __syncthreads();
    }

#pragma unroll
    for (int mi = 0; mi < 2; mi++) {
        int gm0 = block_m + wm * 32 + mi * 16 + gid;
#pragma unroll
        for (int ni = 0; ni < NT; ni++) {
            int gn = block_n + wn * WN + ni * 8 + 2 * tig;
            float bx = 0.f, by = 0.f;
            if (EPI) { bx = bias[gn]; by = bias[gn + 1]; }
            if (gm0 < M) {
                float2 v;
                v.x = acc[mi][ni][0];
                v.y = acc[mi][ni][1];
                if (EPI) { v.x = fmaxf(v.x + bx, 0.f); v.y = fmaxf(v.y + by, 0.f); }
                *(float2*)(C + (size_t)gm0 * N + gn) = v;
            }
            if (gm0 + 8 < M) {
                float2 v;
                v.x = acc[mi][ni][2];
                v.y = acc[mi][ni][3];
                if (EPI) { v.x = fmaxf(v.x + bx, 0.f); v.y = fmaxf(v.y + by, 0.f); }
                *(float2*)(C + (size_t)(gm0 + 8) * N + gn) = v;
            }
        }
    }
}

// ---------------------------------------------------------------------------
// Pooling + classifier
// ---------------------------------------------------------------------------
// graph_ids are sorted: accumulate runs in registers, flush atomics on change.
__global__ void pool_kernel(const float* __restrict__ H, const int* __restrict__ gid) {
    int f = threadIdx.x & 31;
    int w = threadIdx.x >> 5;
    int node0 = blockIdx.x * 64 + w * 8;
    float acc = 0.0f;
    int cur = -1;
#pragma unroll
    for (int i = 0; i < 8; i++) {
        int n = node0 + i;
        if (n >= N_NODES) break;
        int g = __ldg(&gid[n]);
        if (g != cur) {
            if (cur >= 0) atomicAdd(&g_pool[cur * 32 + f], acc);
            cur = g;
            acc = 0.0f;
        }
        acc += H[(size_t)n * 32 + f];
    }
    if (cur >= 0) atomicAdd(&g_pool[cur * 32 + f], acc);
}

__global__ void count_kernel(const int* __restrict__ gid) {
    int n = blockIdx.x * blockDim.x + threadIdx.x;
    if (n < N_NODES) atomicAdd(&g_cnt[gid[n]], 1.0f);
}

__global__ void classify_kernel(const float* __restrict__ Wc, const float* __restrict__ bc,
                                float* __restrict__ out) {
    int i = threadIdx.x;
    if (i < N_GRAPHS * N_CLASSES) {
        int g = i / N_CLASSES, c = i % N_CLASSES;
        float inv_cnt = 1.0f / fmaxf(g_cnt[g], 1.0f);
        float s = 0.0f;
#pragma unroll
        for (int k = 0; k < 32; k++)
            s += (g_pool[g * 32 + k] * inv_cnt) * Wc[k * N_CLASSES + c];
        out[i] = s + bc[c];
    }
}

// ---------------------------------------------------------------------------
// Launch
// ---------------------------------------------------------------------------
extern "C" void kernel_launch(void* const* d_in, const int* in_sizes, int n_in,
                              void* d_out, int out_size) {
    const float* h   = (const float*)d_in[0];
    const int*   src = (const int*)d_in[1];
    const int*   dst = (const int*)d_in[2];
    const int*   gid = (const int*)d_in[3];
    const float* W[6];
    const float* b[6];
    for (int i = 0; i < 6; i++) {
        W[i] = (const float*)d_in[4 + 2 * i];
        b[i] = (const float*)d_in[5 + 2 * i];
    }
    const float* Wc = (const float*)d_in[16];
    const float* bc = (const float*)d_in[17];
    float* out = (float*)d_out;

    float *bufA, *bufB, *wt;
    cudaGetSymbolAddress((void**)&bufA, g_bufA);
    cudaGetSymbolAddress((void**)&bufB, g_bufB);
    cudaGetSymbolAddress((void**)&wt, g_wt);

    const int M = N_NODES;
    const int dims[7] = {512, 1024, 512, 256, 128, 64, 32};
    size_t wt_off[6];
    {
        size_t acc = 0;
        for (int i = 0; i < 6; i++) { wt_off[i] = acc; acc += (size_t)dims[i] * dims[i + 1]; }
    }

    auto smem_bytes = [](int BN) { return 2 * (128 + BN) * 36 * 4; };
    cudaFuncSetAttribute(mma_gemm_kernel<128, true>,  cudaFuncAttributeMaxDynamicSharedMemorySize, smem_bytes(128));
    cudaFuncSetAttribute(mma_gemm_kernel<128, false>, cudaFuncAttributeMaxDynamicSharedMemorySize, smem_bytes(128));
    cudaFuncSetAttribute(mma_gemm_kernel<64,  false>, cudaFuncAttributeMaxDynamicSharedMemorySize, smem_bytes(64));
    cudaFuncSetAttribute(mma_gemm_kernel<32,  false>, cudaFuncAttributeMaxDynamicSharedMemorySize, smem_bytes(32));

    // Graph preprocessing
    init_zero_kernel<<<(N_NODES + 255) / 256, 256>>>();
    degree_kernel<<<(N_EDGES + 255) / 256, 256>>>(src, dst);
    inv_kernel<<<(N_NODES + 255) / 256, 256>>>();
    scan_pass1<<<SCAN_BLK, 1024>>>();
    scan_pass2<<<1, 128>>>();
    scan_pass3<<<SCAN_BLK, 1024>>>();
    bin_kernel<<<(N_EDGES + 255) / 256, 256>>>(src, dst);

    // Weight transposes (tf32-rounded)
    for (int i = 0; i < 6; i++) {
        int kn = dims[i] * dims[i + 1];
        transpose_kernel<<<(kn + 255) / 256, 256>>>(W[i], wt + wt_off[i], dims[i], dims[i + 1]);
    }

    const int MB = (M + 127) / 128;

    // Layer 1: 512 -> 1024 (SpMM first at D=512, 2 feature chunks)
    spmm_kernel<256, false, true><<<dim3(N_NODES, 2), 256>>>(h, bufA, nullptr, 512);
    mma_gemm_kernel<128, true><<<dim3(1024 / 128, MB), 256, smem_bytes(128)>>>(
        bufA, wt + wt_off[0], b[0], bufB, M, 512, 1024);

    // Layer 2: 1024 -> 512
    mma_gemm_kernel<128, false><<<dim3(512 / 128, MB), 256, smem_bytes(128)>>>(
        bufB, wt + wt_off[1], nullptr, bufA, M, 1024, 512);
    spmm_kernel<256, true, true><<<dim3(N_NODES, 2), 256>>>(bufA, bufB, b[1], 512);

    // Layer 3: 512 -> 256
    mma_gemm_kernel<128, false><<<dim3(256 / 128, MB), 256, smem_bytes(128)>>>(
        bufB, wt + wt_off[2], nullptr, bufA, M, 512, 256);
    spmm_kernel<256, true, true><<<dim3(N_NODES, 1), 256>>>(bufA, bufB, b[2], 256);

    // Layer 4: 256 -> 128
    mma_gemm_kernel<128, false><<<dim3(1, MB), 256, smem_bytes(128)>>>(
        bufB, wt + wt_off[3], nullptr, bufA, M, 256, 128);
    spmm_kernel<128, true, true><<<dim3((N_NODES + 1) / 2, 1), 256>>>(bufA, bufB, b[3], 128);

    // Layer 5: 128 -> 64
    mma_gemm_kernel<64, false><<<dim3(1, MB), 256, smem_bytes(64)>>>(
        bufB, wt + wt_off[4], nullptr, bufA, M, 128, 64);
    spmm_kernel<64, true, true><<<dim3((N_NODES + 3) / 4, 1), 256>>>(bufA, bufB, b[4], 64);

    // Layer 6: 64 -> 32 (output feeds pooling: keep full fp32)
    mma_gemm_kernel<32, false><<<dim3(1, MB), 256, smem_bytes(32)>>>(
        bufB, wt + wt_off[5], nullptr, bufA, M, 64, 32);
    spmm_kernel<32, true, false><<<dim3((N_NODES + 7) / 8, 1), 256>>>(bufA, bufB, b[5], 32);

    // Mean pooling + classifier
    pool_kernel<<<(N_NODES + 63) / 64, 256>>>(bufB, gid);
    count_kernel<<<(N_NODES + 255) / 256, 256>>>(gid);
    classify_kernel<<<1, 640>>>(Wc, bc, out);
}

// round 6
// speedup vs baseline: 2.3002x; 2.3002x over previous
#include <cuda_runtime.h>
#include <cuda_fp16.h>
#include <cstddef>
#include <cstdint>

#define N_NODES   100000
#define N_EDGES   3200000
#define N_GRAPHS  64
#define N_CLASSES 10

// ---------------------------------------------------------------------------
// Static device scratch (no allocation allowed)
// ---------------------------------------------------------------------------
__device__ __half g_hA[(size_t)N_NODES * 1024];   // 204.8 MB
__device__ __half g_hB[(size_t)N_NODES * 512];    // 102.4 MB
__device__ float  g_out32[(size_t)N_NODES * 32];  // 12.8 MB (final layer, fp32)
__device__ __half g_wt[1222656];                  // transposed fp16 weights
__device__ int    g_in_deg[N_NODES];
__device__ int    g_out_deg[N_NODES];
__device__ float  g_in_inv[N_NODES];
__device__ float  g_out_inv[N_NODES];
__device__ int    g_row_off[N_NODES + 1];
__device__ int    g_cursor[N_NODES];
__device__ int    g_csr_src[N_EDGES];
__device__ int    g_blocksum[128];
__device__ int    g_blockoff[128];
__device__ float  g_pool[N_GRAPHS * 32];
__device__ float  g_cnt[N_GRAPHS];

// ---------------------------------------------------------------------------
// Helpers (family-portable: cp.async + mma.sync fp16)
// ---------------------------------------------------------------------------
__device__ __forceinline__ void cp16(uint32_t dst, const void* src, bool valid) {
    asm volatile("cp.async.cg.shared.global [%0], [%1], 16, %2;"
                 :: "r"(dst), "l"(src), "r"(valid ? 16 : 0));
}
#define CP_COMMIT() asm volatile("cp.async.commit_group;" ::: "memory")
#define CP_WAIT(n)  asm volatile("cp.async.wait_group %0;" :: "n"(n) : "memory")

__device__ __forceinline__ void mma_f16(float* d, const uint32_t* a,
                                        uint32_t b0, uint32_t b1) {
    asm volatile(
        "mma.sync.aligned.m16n8k16.row.col.f32.f16.f16.f32 "
        "{%0,%1,%2,%3}, {%4,%5,%6,%7}, {%8,%9}, {%0,%1,%2,%3};"
        : "+f"(d[0]), "+f"(d[1]), "+f"(d[2]), "+f"(d[3])
        : "r"(a[0]), "r"(a[1]), "r"(a[2]), "r"(a[3]), "r"(b0), "r"(b1));
}

// ---------------------------------------------------------------------------
// Preprocessing
// ---------------------------------------------------------------------------
__global__ void init_zero_kernel() {
    int i = blockIdx.x * blockDim.x + threadIdx.x;
    if (i < N_NODES) { g_in_deg[i] = 0; g_out_deg[i] = 0; g_cursor[i] = 0; }
    if (i < N_GRAPHS * 32) g_pool[i] = 0.0f;
    if (i < N_GRAPHS) g_cnt[i] = 0.0f;
}

__global__ void degree_kernel(const int* __restrict__ src, const int* __restrict__ dst) {
    int e = blockIdx.x * blockDim.x + threadIdx.x;
    if (e < N_EDGES) {
        atomicAdd(&g_out_deg[src[e]], 1);
        atomicAdd(&g_in_deg[dst[e]], 1);
    }
}

__global__ void inv_kernel() {
    int i = blockIdx.x * blockDim.x + threadIdx.x;
    if (i < N_NODES) {
        g_out_inv[i] = rsqrtf(fmaxf((float)g_out_deg[i], 1.0f));
        g_in_inv[i]  = rsqrtf(fmaxf((float)g_in_deg[i], 1.0f));
    }
}

#define SCAN_BLK 98
__global__ void scan_pass1() {
    __shared__ int temp[1024];
    int tid = threadIdx.x;
    int i = blockIdx.x * 1024 + tid;
    int v = (i < N_NODES) ? g_in_deg[i] : 0;
    temp[tid] = v;
    __syncthreads();
    for (int off = 1; off < 1024; off <<= 1) {
        int t = (tid >= off) ? temp[tid - off] : 0;
        __syncthreads();
        temp[tid] += t;
        __syncthreads();
    }
    if (i < N_NODES) g_row_off[i] = temp[tid] - v;
    if (tid == 1023) g_blocksum[blockIdx.x] = temp[1023];
}

__global__ void scan_pass2() {
    __shared__ int s[SCAN_BLK];
    int tid = threadIdx.x;
    if (tid < SCAN_BLK) s[tid] = g_blocksum[tid];
    __syncthreads();
    if (tid == 0) {
        int acc = 0;
        for (int b = 0; b < SCAN_BLK; b++) { int t = s[b]; s[b] = acc; acc += t; }
        g_row_off[N_NODES] = acc;
    }
    __syncthreads();
    if (tid < SCAN_BLK) g_blockoff[tid] = s[tid];
}

__global__ void scan_pass3() {
    int i = blockIdx.x * 1024 + threadIdx.x;
    if (i < N_NODES) g_row_off[i] += g_blockoff[blockIdx.x];
}

__global__ void bin_kernel(const int* __restrict__ src, const int* __restrict__ dst) {
    int e = blockIdx.x * blockDim.x + threadIdx.x;
    if (e < N_EDGES) {
        int d = dst[e];
        int pos = g_row_off[d] + atomicAdd(&g_cursor[d], 1);
        g_csr_src[pos] = src[e];
    }
}

// W[k][n] (fp32) -> Wt[n][k] (fp16)
__global__ void transpose_kernel(const float* __restrict__ W, __half* __restrict__ Wt,
                                 int K, int N) {
    int i = blockIdx.x * blockDim.x + threadIdx.x;
    if (i < K * N) {
        int k = i / N, n = i % N;
        Wt[(size_t)n * K + k] = __float2half_rn(W[i]);
    }
}

// fp32 -> fp16 bulk convert (input features)
__global__ void f2h_kernel(const float* __restrict__ x, __half* __restrict__ y) {
    size_t i = ((size_t)blockIdx.x * blockDim.x + threadIdx.x) * 4;
    if (i < (size_t)N_NODES * 512) {
        float4 v = *(const float4*)(x + i);
        __half2* yp = (__half2*)(y + i);
        yp[0] = __floats2half2_rn(v.x, v.y);
        yp[1] = __floats2half2_rn(v.z, v.w);
    }
}

// ---------------------------------------------------------------------------
// SpMM (fp16 gather, fp32 accumulate):
//   Y[n] = in_inv[n] * sum_{s in N(n)} out_inv[s] * X[s]  (+bias, relu)
// Each thread owns 8 consecutive halfs (one 16B load per edge), edge loop
// unrolled x2 for MLP.
// ---------------------------------------------------------------------------
template <int D, bool EPI, bool OUT32>
__global__ void spmm_kernel(const __half* __restrict__ X, void* __restrict__ Yv,
                            const float* __restrict__ bias) {
    constexpr int TPN = D / 8;          // threads per node
    constexpr int NPB = 256 / TPN;      // nodes per block
    int node = blockIdx.x * NPB + threadIdx.x / TPN;
    if (node >= N_NODES) return;
    int f0 = (threadIdx.x % TPN) * 8;

    float acc[8];
#pragma unroll
    for (int i = 0; i < 8; i++) acc[i] = 0.0f;

    int s0 = g_row_off[node];
    int s1 = g_row_off[node + 1];
    const __half* Xf = X + f0;
    int j = s0;
    for (; j + 2 <= s1; j += 2) {
        int sA = __ldg(&g_csr_src[j]);
        int sB = __ldg(&g_csr_src[j + 1]);
        float wA = __ldg(&g_out_inv[sA]);
        float wB = __ldg(&g_out_inv[sB]);
        float4 pA = *(const float4*)(Xf + (size_t)sA * D);
        float4 pB = *(const float4*)(Xf + (size_t)sB * D);
        const __half2* a2 = (const __half2*)&pA;
        const __half2* b2 = (const __half2*)&pB;
#pragma unroll
        for (int i = 0; i < 4; i++) {
            float2 fa = __half22float2(a2[i]);
            float2 fb = __half22float2(b2[i]);
            acc[2 * i]     += wA * fa.x + wB * fb.x;
            acc[2 * i + 1] += wA * fa.y + wB * fb.y;
        }
    }
    if (j < s1) {
        int s = __ldg(&g_csr_src[j]);
        float w = __ldg(&g_out_inv[s]);
        float4 p = *(const float4*)(Xf + (size_t)s * D);
        const __half2* a2 = (const __half2*)&p;
#pragma unroll
        for (int i = 0; i < 4; i++) {
            float2 fa = __half22float2(a2[i]);
            acc[2 * i]     += w * fa.x;
            acc[2 * i + 1] += w * fa.y;
        }
    }

    float win = g_in_inv[node];
#pragma unroll
    for (int i = 0; i < 8; i++) {
        float v = acc[i] * win;
        if (EPI) v = fmaxf(v + bias[f0 + i], 0.0f);
        acc[i] = v;
    }

    if (OUT32) {
        float* Y = (float*)Yv + (size_t)node * D + f0;
        *(float4*)(Y + 0) = make_float4(acc[0], acc[1], acc[2], acc[3]);
        *(float4*)(Y + 4) = make_float4(acc[4], acc[5], acc[6], acc[7]);
    } else {
        __half2 o[4];
#pragma unroll
        for (int i = 0; i < 4; i++) o[i] = __floats2half2_rn(acc[2 * i], acc[2 * i + 1]);
        *(float4*)((__half*)Yv + (size_t)node * D + f0) = *(float4*)o;
    }
}

// ---------------------------------------------------------------------------
// fp16 mma.sync GEMM: C[M,N] = A[M,K] @ Bt[N,K]^T  (+bias, relu), fp32 accum.
// 128 x BN tile, BK=32 halfs, 256 thr (warps 4x2), cp.async double-buffered.
// ---------------------------------------------------------------------------
template <int BN, bool EPI>
__global__ void __launch_bounds__(256)
mma_gemm_kernel(const __half* __restrict__ A, const __half* __restrict__ Bt,
                const float* __restrict__ bias, __half* __restrict__ C,
                int M, int K, int N) {
    extern __shared__ __half smh[];
    constexpr int LD = 40;                 // padded row (halfs): conflict-free LDS.32
    constexpr int A_HALFS = 128 * LD;
    constexpr int B_HALFS = BN * LD;
    constexpr int STAGE = A_HALFS + B_HALFS;
    constexpr int WN = BN / 2;
    constexpr int NT = WN / 8;

    int tid = threadIdx.x;
    int lane = tid & 31, w = tid >> 5;
    int wm = w & 3, wn = w >> 2;
    int gid = lane >> 2, tig = lane & 3;
    int block_m = blockIdx.y * 128;
    int block_n = blockIdx.x * BN;

    uint32_t sm_u32 = (uint32_t)__cvta_generic_to_shared(smh);
    const int nChunks = K >> 5;

    auto load_stage = [&](int c, int buf) {
        int k0 = c << 5;
        uint32_t abase = sm_u32 + buf * STAGE * 2;
        uint32_t bbase = abase + A_HALFS * 2;
        // A: 128 rows x 4 x 16B
#pragma unroll
        for (int t = 0; t < 2; t++) {
            int idx = tid + t * 256;
            int row = idx >> 2, c4 = idx & 3;
            int gm = block_m + row;
            cp16(abase + (row * LD + c4 * 8) * 2,
                 A + (size_t)gm * K + k0 + c4 * 8, gm < M);
        }
        // B: BN rows x 4 x 16B
#pragma unroll
        for (int t = 0; t < (BN * 4 + 255) / 256; t++) {
            int idx = tid + t * 256;
            if (idx < BN * 4) {
                int row = idx >> 2, c4 = idx & 3;
                cp16(bbase + (row * LD + c4 * 8) * 2,
                     Bt + (size_t)(block_n + row) * K + k0 + c4 * 8, true);
            }
        }
        CP_COMMIT();
    };

    float acc[2][NT][4];
#pragma unroll
    for (int mi = 0; mi < 2; mi++)
#pragma unroll
        for (int ni = 0; ni < NT; ni++)
#pragma unroll
            for (int j = 0; j < 4; j++) acc[mi][ni][j] = 0.0f;

    load_stage(0, 0);

    for (int c = 0; c < nChunks; c++) {
        if (c + 1 < nChunks) {
            load_stage(c + 1, (c + 1) & 1);
            CP_WAIT(1);
        } else {
            CP_WAIT(0);
        }
        __syncthreads();

        const __half* AsC = smh + (c & 1) * STAGE;
        const __half* BsC = AsC + A_HALFS;

#pragma unroll
        for (int kk = 0; kk < 2; kk++) {
            uint32_t af[2][4];
#pragma unroll
            for (int mi = 0; mi < 2; mi++) {
                int r0 = wm * 32 + mi * 16 + gid;
                af[mi][0] = *(const uint32_t*)&AsC[r0 * LD + kk * 16 + 2 * tig];
                af[mi][1] = *(const uint32_t*)&AsC[(r0 + 8) * LD + kk * 16 + 2 * tig];
                af[mi][2] = *(const uint32_t*)&AsC[r0 * LD + kk * 16 + 8 + 2 * tig];
                af[mi][3] = *(const uint32_t*)&AsC[(r0 + 8) * LD + kk * 16 + 8 + 2 * tig];
            }
#pragma unroll
            for (int ni = 0; ni < NT; ni++) {
                int br = wn * WN + ni * 8 + gid;
                uint32_t b0 = *(const uint32_t*)&BsC[br * LD + kk * 16 + 2 * tig];
                uint32_t b1 = *(const uint32_t*)&BsC[br * LD + kk * 16 + 8 + 2 * tig];
                mma_f16(acc[0][ni], af[0], b0, b1);
                mma_f16(acc[1][ni], af[1], b0, b1);
            }
        }
        __syncthreads();
    }

    // epilogue: fp32 accum -> (+bias, relu) -> fp16 stores
#pragma unroll
    for (int mi = 0; mi < 2; mi++) {
        int gm0 = block_m + wm * 32 + mi * 16 + gid;
#pragma unroll
        for (int ni = 0; ni < NT; ni++) {
            int gn = block_n + wn * WN + ni * 8 + 2 * tig;
            float bx = 0.f, by = 0.f;
            if (EPI) { bx = bias[gn]; by = bias[gn + 1]; }
            if (gm0 < M) {
                float vx = acc[mi][ni][0], vy = acc[mi][ni][1];
                if (EPI) { vx = fmaxf(vx + bx, 0.f); vy = fmaxf(vy + by, 0.f); }
                *(__half2*)(C + (size_t)gm0 * N + gn) = __floats2half2_rn(vx, vy);
            }
            if (gm0 + 8 < M) {
                float vx = acc[mi][ni][2], vy = acc[mi][ni][3];
                if (EPI) { vx = fmaxf(vx + bx, 0.f); vy = fmaxf(vy + by, 0.f); }
                *(__half2*)(C + (size_t)(gm0 + 8) * N + gn) = __floats2half2_rn(vx, vy);
            }
        }
    }
}

// ---------------------------------------------------------------------------
// Pooling + classifier (gid sorted: register-accumulate runs, flush on change)
// ---------------------------------------------------------------------------
__global__ void pool_kernel(const float* __restrict__ H, const int* __restrict__ gid) {
    int f = threadIdx.x & 31;
    int w = threadIdx.x >> 5;
    int node0 = blockIdx.x * 64 + w * 8;
    float acc = 0.0f;
    int cur = -1;
#pragma unroll
    for (int i = 0; i < 8; i++) {
        int n = node0 + i;
        if (n >= N_NODES) break;
        int g = __ldg(&gid[n]);
        if (g != cur) {
            if (cur >= 0) atomicAdd(&g_pool[cur * 32 + f], acc);
            cur = g;
            acc = 0.0f;
        }
        acc += H[(size_t)n * 32 + f];
    }
    if (cur >= 0) atomicAdd(&g_pool[cur * 32 + f], acc);
}

__global__ void count_kernel(const int* __restrict__ gid) {
    int n = blockIdx.x * blockDim.x + threadIdx.x;
    if (n < N_NODES) atomicAdd(&g_cnt[gid[n]], 1.0f);
}

__global__ void classify_kernel(const float* __restrict__ Wc, const float* __restrict__ bc,
                                float* __restrict__ out) {
    int i = threadIdx.x;
    if (i < N_GRAPHS * N_CLASSES) {
        int g = i / N_CLASSES, c = i % N_CLASSES;
        float inv_cnt = 1.0f / fmaxf(g_cnt[g], 1.0f);
        float s = 0.0f;
#pragma unroll
        for (int k = 0; k < 32; k++)
            s += (g_pool[g * 32 + k] * inv_cnt) * Wc[k * N_CLASSES + c];
        out[i] = s + bc[c];
    }
}

// ---------------------------------------------------------------------------
// Launch
// ---------------------------------------------------------------------------
extern "C" void kernel_launch(void* const* d_in, const int* in_sizes, int n_in,
                              void* d_out, int out_size) {
    const float* h   = (const float*)d_in[0];
    const int*   src = (const int*)d_in[1];
    const int*   dst = (const int*)d_in[2];
    const int*   gid = (const int*)d_in[3];
    const float* W[6];
    const float* b[6];
    for (int i = 0; i < 6; i++) {
        W[i] = (const float*)d_in[4 + 2 * i];
        b[i] = (const float*)d_in[5 + 2 * i];
    }
    const float* Wc = (const float*)d_in[16];
    const float* bc = (const float*)d_in[17];
    float* out = (float*)d_out;

    __half *hA, *hB, *wt;
    float* out32;
    cudaGetSymbolAddress((void**)&hA, g_hA);
    cudaGetSymbolAddress((void**)&hB, g_hB);
    cudaGetSymbolAddress((void**)&wt, g_wt);
    cudaGetSymbolAddress((void**)&out32, g_out32);

    const int M = N_NODES;
    const int dims[7] = {512, 1024, 512, 256, 128, 64, 32};
    size_t wt_off[6];
    {
        size_t acc = 0;
        for (int i = 0; i < 6; i++) { wt_off[i] = acc; acc += (size_t)dims[i] * dims[i + 1]; }
    }

    auto smem_bytes = [](int BN) { return 2 * (128 + BN) * 40 * 2; };
    cudaFuncSetAttribute(mma_gemm_kernel<128, true>,  cudaFuncAttributeMaxDynamicSharedMemorySize, smem_bytes(128));
    cudaFuncSetAttribute(mma_gemm_kernel<128, false>, cudaFuncAttributeMaxDynamicSharedMemorySize, smem_bytes(128));
    cudaFuncSetAttribute(mma_gemm_kernel<64,  false>, cudaFuncAttributeMaxDynamicSharedMemorySize, smem_bytes(64));
    cudaFuncSetAttribute(mma_gemm_kernel<32,  false>, cudaFuncAttributeMaxDynamicSharedMemorySize, smem_bytes(32));

    // Graph preprocessing
    init_zero_kernel<<<(N_NODES + 255) / 256, 256>>>();
    degree_kernel<<<(N_EDGES + 255) / 256, 256>>>(src, dst);
    inv_kernel<<<(N_NODES + 255) / 256, 256>>>();
    scan_pass1<<<SCAN_BLK, 1024>>>();
    scan_pass2<<<1, 128>>>();
    scan_pass3<<<SCAN_BLK, 1024>>>();
    bin_kernel<<<(N_EDGES + 255) / 256, 256>>>(src, dst);

    // Weight transposes (fp32 -> fp16, [K,N] -> [N,K])
    for (int i = 0; i < 6; i++) {
        int kn = dims[i] * dims[i + 1];
        transpose_kernel<<<(kn + 255) / 256, 256>>>(W[i], wt + wt_off[i], dims[i], dims[i + 1]);
    }

    // Input features fp32 -> fp16
    f2h_kernel<<<(N_NODES * 512 / 4 + 255) / 256, 256>>>(h, hA);

    const int MB = (M + 127) / 128;

    // Layer 1: 512 -> 1024 (SpMM first, then GEMM + bias + relu)
    spmm_kernel<512, false, false><<<(N_NODES + 3) / 4, 256>>>(hA, hB, nullptr);
    mma_gemm_kernel<128, true><<<dim3(1024 / 128, MB), 256, smem_bytes(128)>>>(
        hB, wt + wt_off[0], b[0], hA, M, 512, 1024);

    // Layer 2: 1024 -> 512
    mma_gemm_kernel<128, false><<<dim3(512 / 128, MB), 256, smem_bytes(128)>>>(
        hA, wt + wt_off[1], nullptr, hB, M, 1024, 512);
    spmm_kernel<512, true, false><<<(N_NODES + 3) / 4, 256>>>(hB, hA, b[1]);

    // Layer 3: 512 -> 256
    mma_gemm_kernel<128, false><<<dim3(256 / 128, MB), 256, smem_bytes(128)>>>(
        hA, wt + wt_off[2], nullptr, hB, M, 512, 256);
    spmm_kernel<256, true, false><<<(N_NODES + 7) / 8, 256>>>(hB, hA, b[2]);

    // Layer 4: 256 -> 128
    mma_gemm_kernel<128, false><<<dim3(1, MB), 256, smem_bytes(128)>>>(
        hA, wt + wt_off[3], nullptr, hB, M, 256, 128);
    spmm_kernel<128, true, false><<<(N_NODES + 15) / 16, 256>>>(hB, hA, b[3]);

    // Layer 5: 128 -> 64
    mma_gemm_kernel<64, false><<<dim3(1, MB), 256, smem_bytes(64)>>>(
        hA, wt + wt_off[4], nullptr, hB, M, 128, 64);
    spmm_kernel<64, true, false><<<(N_NODES + 31) / 32, 256>>>(hB, hA, b[4]);

    // Layer 6: 64 -> 32 (SpMM emits fp32 for pooling)
    mma_gemm_kernel<32, false><<<dim3(1, MB), 256, smem_bytes(32)>>>(
        hA, wt + wt_off[5], nullptr, hB, M, 64, 32);
    spmm_kernel<32, true, true><<<(N_NODES + 63) / 64, 256>>>(hB, out32, b[5]);

    // Mean pooling + classifier
    pool_kernel<<<(N_NODES + 63) / 64, 256>>>(out32, gid);
    count_kernel<<<(N_NODES + 255) / 256, 256>>>(gid);
    classify_kernel<<<1, 640>>>(Wc, bc, out);
}

// round 11
// speedup vs baseline: 2.5609x; 1.1133x over previous
#include <cuda_runtime.h>
#include <cuda_fp16.h>
#include <cstddef>
#include <cstdint>

#define N_NODES   100000
#define N_EDGES   3200000
#define N_GRAPHS  64
#define N_CLASSES 10

// ---------------------------------------------------------------------------
// Static device scratch (no allocation allowed)
// ---------------------------------------------------------------------------
__device__ __half g_hA[(size_t)N_NODES * 1024];   // 204.8 MB
__device__ __half g_hB[(size_t)N_NODES * 512];    // 102.4 MB
__device__ float  g_out32[(size_t)N_NODES * 32];  // 12.8 MB (final layer, fp32)
__device__ __half g_wt[1222656];                  // transposed fp16 weights
__device__ int    g_in_deg[N_NODES];
__device__ int    g_out_deg[N_NODES];
__device__ float  g_in_inv[N_NODES];
__device__ float  g_out_inv[N_NODES];
__device__ int    g_row_off[N_NODES + 1];
__device__ int    g_cursor[N_NODES];
__device__ int    g_csr_src[N_EDGES];
__device__ int    g_blocksum[128];
__device__ int    g_blockoff[128];
__device__ float  g_pool[N_GRAPHS * 32];
__device__ float  g_cnt[N_GRAPHS];

// ---------------------------------------------------------------------------
// Helpers (family-portable: cp.async + ldmatrix + mma.sync fp16)
// ---------------------------------------------------------------------------
__device__ __forceinline__ void cp16(uint32_t dst, const void* src, bool valid) {
    asm volatile("cp.async.cg.shared.global [%0], [%1], 16, %2;"
                 :: "r"(dst), "l"(src), "r"(valid ? 16 : 0));
}
#define CP_COMMIT() asm volatile("cp.async.commit_group;" ::: "memory")
#define CP_WAIT(n)  asm volatile("cp.async.wait_group %0;" :: "n"(n) : "memory")

__device__ __forceinline__ void ldsm_x4(uint32_t& r0, uint32_t& r1,
                                        uint32_t& r2, uint32_t& r3, uint32_t addr) {
    asm volatile("ldmatrix.sync.aligned.m8n8.x4.shared.b16 {%0,%1,%2,%3}, [%4];"
                 : "=r"(r0), "=r"(r1), "=r"(r2), "=r"(r3) : "r"(addr));
}

__device__ __forceinline__ void mma_f16(float* d, const uint32_t* a,
                                        uint32_t b0, uint32_t b1) {
    asm volatile(
        "mma.sync.aligned.m16n8k16.row.col.f32.f16.f16.f32 "
        "{%0,%1,%2,%3}, {%4,%5,%6,%7}, {%8,%9}, {%0,%1,%2,%3};"
        : "+f"(d[0]), "+f"(d[1]), "+f"(d[2]), "+f"(d[3])
        : "r"(a[0]), "r"(a[1]), "r"(a[2]), "r"(a[3]), "r"(b0), "r"(b1));
}

// ---------------------------------------------------------------------------
// Preprocessing
// ---------------------------------------------------------------------------
__global__ void init_zero_kernel() {
    int i = blockIdx.x * blockDim.x + threadIdx.x;
    if (i < N_NODES) { g_in_deg[i] = 0; g_out_deg[i] = 0; g_cursor[i] = 0; }
    if (i < N_GRAPHS * 32) g_pool[i] = 0.0f;
    if (i < N_GRAPHS) g_cnt[i] = 0.0f;
}

__global__ void degree_kernel(const int* __restrict__ src, const int* __restrict__ dst) {
    int e = blockIdx.x * blockDim.x + threadIdx.x;
    if (e < N_EDGES) {
        atomicAdd(&g_out_deg[src[e]], 1);
        atomicAdd(&g_in_deg[dst[e]], 1);
    }
}

#define SCAN_BLK 98
__global__ void scan_pass1() {
    __shared__ int temp[1024];
    int tid = threadIdx.x;
    int i = blockIdx.x * 1024 + tid;
    int v = (i < N_NODES) ? g_in_deg[i] : 0;
    temp[tid] = v;
    __syncthreads();
    for (int off = 1; off < 1024; off <<= 1) {
        int t = (tid >= off) ? temp[tid - off] : 0;
        __syncthreads();
        temp[tid] += t;
        __syncthreads();
    }
    if (i < N_NODES) g_row_off[i] = temp[tid] - v;
    if (tid == 1023) g_blocksum[blockIdx.x] = temp[1023];
}

__global__ void scan_pass2() {
    __shared__ int s[SCAN_BLK];
    int tid = threadIdx.x;
    if (tid < SCAN_BLK) s[tid] = g_blocksum[tid];
    __syncthreads();
    if (tid == 0) {
        int acc = 0;
        for (int b = 0; b < SCAN_BLK; b++) { int t = s[b]; s[b] = acc; acc += t; }
        g_row_off[N_NODES] = acc;
    }
    __syncthreads();
    if (tid < SCAN_BLK) g_blockoff[tid] = s[tid];
}

// pass3 also computes the inverse-sqrt degree scalings (folded kernel)
__global__ void scan_pass3() {
    int i = blockIdx.x * 1024 + threadIdx.x;
    if (i < N_NODES) {
        g_row_off[i] += g_blockoff[blockIdx.x];
        g_out_inv[i] = rsqrtf(fmaxf((float)g_out_deg[i], 1.0f));
        g_in_inv[i]  = rsqrtf(fmaxf((float)g_in_deg[i], 1.0f));
    }
}

__global__ void bin_kernel(const int* __restrict__ src, const int* __restrict__ dst) {
    int e = blockIdx.x * blockDim.x + threadIdx.x;
    if (e < N_EDGES) {
        int d = dst[e];
        int pos = g_row_off[d] + atomicAdd(&g_cursor[d], 1);
        g_csr_src[pos] = src[e];
    }
}

// W[k][n] (fp32) -> Wt[n][k] (fp16)
__global__ void transpose_kernel(const float* __restrict__ W, __half* __restrict__ Wt,
                                 int K, int N) {
    int i = blockIdx.x * blockDim.x + threadIdx.x;
    if (i < K * N) {
        int k = i / N, n = i % N;
        Wt[(size_t)n * K + k] = __float2half_rn(W[i]);
    }
}

// fp32 -> fp16 bulk convert (input features)
__global__ void f2h_kernel(const float* __restrict__ x, __half* __restrict__ y) {
    size_t i = ((size_t)blockIdx.x * blockDim.x + threadIdx.x) * 4;
    if (i < (size_t)N_NODES * 512) {
        float4 v = *(const float4*)(x + i);
        __half2* yp = (__half2*)(y + i);
        yp[0] = __floats2half2_rn(v.x, v.y);
        yp[1] = __floats2half2_rn(v.z, v.w);
    }
}

// ---------------------------------------------------------------------------
// SpMM (fp16 gather, fp32 accumulate):
//   Y[n] = in_inv[n] * sum_{s in N(n)} out_inv[s] * X[s]  (+bias, relu)
// Each thread owns 8 consecutive halfs (one 16B load per edge); edge loop
// unrolled x4 for MLP. Outputs use evict-first (__stcs) stores so the gather
// table X stays L2-resident.
// ---------------------------------------------------------------------------
template <int D, bool EPI, bool OUT32>
__global__ void spmm_kernel(const __half* __restrict__ X, void* __restrict__ Yv,
                            const float* __restrict__ bias) {
    constexpr int TPN = D / 8;          // threads per node
    constexpr int NPB = 256 / TPN;      // nodes per block
    int node = blockIdx.x * NPB + threadIdx.x / TPN;
    if (node >= N_NODES) return;
    int f0 = (threadIdx.x % TPN) * 8;

    float acc[8];
#pragma unroll
    for (int i = 0; i < 8; i++) acc[i] = 0.0f;

    int s0 = g_row_off[node];
    int s1 = g_row_off[node + 1];
    const __half* Xf = X + f0;
    int j = s0;
    for (; j + 4 <= s1; j += 4) {
        int sA = __ldg(&g_csr_src[j]);
        int sB = __ldg(&g_csr_src[j + 1]);
        int sC = __ldg(&g_csr_src[j + 2]);
        int sD = __ldg(&g_csr_src[j + 3]);
        float wA = __ldg(&g_out_inv[sA]);
        float wB = __ldg(&g_out_inv[sB]);
        float wC = __ldg(&g_out_inv[sC]);
        float wD = __ldg(&g_out_inv[sD]);
        float4 pA = *(const float4*)(Xf + (size_t)sA * D);
        float4 pB = *(const float4*)(Xf + (size_t)sB * D);
        float4 pC = *(const float4*)(Xf + (size_t)sC * D);
        float4 pD = *(const float4*)(Xf + (size_t)sD * D);
        const __half2* a2 = (const __half2*)&pA;
        const __half2* b2 = (const __half2*)&pB;
        const __half2* c2 = (const __half2*)&pC;
        const __half2* d2 = (const __half2*)&pD;
#pragma unroll
        for (int i = 0; i < 4; i++) {
            float2 fa = __half22float2(a2[i]);
            float2 fb = __half22float2(b2[i]);
            float2 fc = __half22float2(c2[i]);
            float2 fd = __half22float2(d2[i]);
            acc[2 * i]     += wA * fa.x + wB * fb.x + wC * fc.x + wD * fd.x;
            acc[2 * i + 1] += wA * fa.y + wB * fb.y + wC * fc.y + wD * fd.y;
        }
    }
    for (; j < s1; j++) {
        int s = __ldg(&g_csr_src[j]);
        float w = __ldg(&g_out_inv[s]);
        float4 p = *(const float4*)(Xf + (size_t)s * D);
        const __half2* a2 = (const __half2*)&p;
#pragma unroll
        for (int i = 0; i < 4; i++) {
            float2 fa = __half22float2(a2[i]);
            acc[2 * i]     += w * fa.x;
            acc[2 * i + 1] += w * fa.y;
        }
    }

    float win = g_in_inv[node];
#pragma unroll
    for (int i = 0; i < 8; i++) {
        float v = acc[i] * win;
        if (EPI) v = fmaxf(v + bias[f0 + i], 0.0f);
        acc[i] = v;
    }

    if (OUT32) {
        float* Y = (float*)Yv + (size_t)node * D + f0;
        __stcs((float4*)(Y + 0), make_float4(acc[0], acc[1], acc[2], acc[3]));
        __stcs((float4*)(Y + 4), make_float4(acc[4], acc[5], acc[6], acc[7]));
    } else {
        __half2 o[4];
#pragma unroll
        for (int i = 0; i < 4; i++) o[i] = __floats2half2_rn(acc[2 * i], acc[2 * i + 1]);
        __stcs((float4*)((__half*)Yv + (size_t)node * D + f0), *(float4*)o);
    }
}

// ---------------------------------------------------------------------------
// fp16 mma.sync GEMM: C[M,N] = A[M,K] @ Bt[N,K]^T  (+bias, relu), fp32 accum.
// 128 x BN tile, BK=32 halfs, 256 thr (warps 4x2), 3-stage cp.async pipeline,
// ldmatrix fragment loads (LD=40 padding -> conflict-free LDSM phases).
// ---------------------------------------------------------------------------
template <int BN, bool EPI>
__global__ void __launch_bounds__(256)
mma_gemm_kernel(const __half* __restrict__ A, const __half* __restrict__ Bt,
                const float* __restrict__ bias, __half* __restrict__ C,
                int M, int K, int N) {
    extern __shared__ __half smh[];
    constexpr int LD = 40;
    constexpr int A_HALFS = 128 * LD;
    constexpr int B_HALFS = BN * LD;
    constexpr int STAGE = A_HALFS + B_HALFS;
    constexpr int WN = BN / 2;
    constexpr int NT = WN / 8;

    int tid = threadIdx.x;
    int lane = tid & 31, w = tid >> 5;
    int wm = w & 3, wn = w >> 2;
    int gid = lane >> 2, tig = lane & 3;
    int block_m = blockIdx.y * 128;
    int block_n = blockIdx.x * BN;

    uint32_t sm_u32 = (uint32_t)__cvta_generic_to_shared(smh);
    const int nChunks = K >> 5;

    auto load_stage = [&](int c, int buf) {
        int k0 = c << 5;
        uint32_t abase = sm_u32 + buf * STAGE * 2;
        uint32_t bbase = abase + A_HALFS * 2;
#pragma unroll
        for (int t = 0; t < 2; t++) {
            int idx = tid + t * 256;
            int row = idx >> 2, c4 = idx & 3;
            int gm = block_m + row;
            cp16(abase + (row * LD + c4 * 8) * 2,
                 A + (size_t)gm * K + k0 + c4 * 8, gm < M);
        }
#pragma unroll
        for (int t = 0; t < (BN * 4 + 255) / 256; t++) {
            int idx = tid + t * 256;
            if (idx < BN * 4) {
                int row = idx >> 2, c4 = idx & 3;
                cp16(bbase + (row * LD + c4 * 8) * 2,
                     Bt + (size_t)(block_n + row) * K + k0 + c4 * 8, true);
            }
        }
        CP_COMMIT();
    };

    float acc[2][NT][4];
#pragma unroll
    for (int mi = 0; mi < 2; mi++)
#pragma unroll
        for (int ni = 0; ni < NT; ni++)
#pragma unroll
            for (int j = 0; j < 4; j++) acc[mi][ni][j] = 0.0f;

    // ldmatrix lane-address components
    int a_row = (lane & 7) + ((lane >> 3) & 1) * 8;  // 0..15
    int a_kh  = (lane >> 4) * 8;                     // 0 or 8
    int b_row = (lane & 7) + ((lane >> 4) & 1) * 8;  // 0..15
    int b_kh  = ((lane >> 3) & 1) * 8;               // 0 or 8

    load_stage(0, 0);
    if (nChunks > 1) load_stage(1, 1);

    for (int c = 0; c < nChunks; c++) {
        if (c + 1 < nChunks) { CP_WAIT(1); } else { CP_WAIT(0); }
        __syncthreads();

        if (c + 2 < nChunks) load_stage(c + 2, (c + 2) % 3);

        int buf = c % 3;
        uint32_t As = sm_u32 + buf * STAGE * 2;
        uint32_t Bs = As + A_HALFS * 2;

#pragma unroll
        for (int kk = 0; kk < 2; kk++) {
            uint32_t af[2][4];
#pragma unroll
            for (int mi = 0; mi < 2; mi++) {
                uint32_t addr = As + (((wm * 32 + mi * 16 + a_row) * LD) + kk * 16 + a_kh) * 2;
                ldsm_x4(af[mi][0], af[mi][1], af[mi][2], af[mi][3], addr);
            }
            uint32_t bf[NT][2];
#pragma unroll
            for (int nj = 0; nj < NT / 2; nj++) {
                uint32_t addr = Bs + (((wn * WN + nj * 16 + b_row) * LD) + kk * 16 + b_kh) * 2;
                ldsm_x4(bf[2 * nj][0], bf[2 * nj][1], bf[2 * nj + 1][0], bf[2 * nj + 1][1], addr);
            }
#pragma unroll
            for (int ni = 0; ni < NT; ni++) {
                mma_f16(acc[0][ni], af[0], bf[ni][0], bf[ni][1]);
                mma_f16(acc[1][ni], af[1], bf[ni][0], bf[ni][1]);
            }
        }
        __syncthreads();
    }

    // epilogue: fp32 accum -> (+bias, relu) -> fp16 stores
#pragma unroll
    for (int mi = 0; mi < 2; mi++) {
        int gm0 = block_m + wm * 32 + mi * 16 + gid;
#pragma unroll
        for (int ni = 0; ni < NT; ni++) {
            int gn = block_n + wn * WN + ni * 8 + 2 * tig;
            float bx = 0.f, by = 0.f;
            if (EPI) { bx = bias[gn]; by = bias[gn + 1]; }
            if (gm0 < M) {
                float vx = acc[mi][ni][0], vy = acc[mi][ni][1];
                if (EPI) { vx = fmaxf(vx + bx, 0.f); vy = fmaxf(vy + by, 0.f); }
                *(__half2*)(C + (size_t)gm0 * N + gn) = __floats2half2_rn(vx, vy);
            }
            if (gm0 + 8 < M) {
                float vx = acc[mi][ni][2], vy = acc[mi][ni][3];
                if (EPI) { vx = fmaxf(vx + bx, 0.f); vy = fmaxf(vy + by, 0.f); }
                *(__half2*)(C + (size_t)(gm0 + 8) * N + gn) = __floats2half2_rn(vx, vy);
            }
        }
    }
}

// ---------------------------------------------------------------------------
// Pooling + classifier (gid sorted: register-accumulate runs, flush on change)
// ---------------------------------------------------------------------------
__global__ void pool_kernel(const float* __restrict__ H, const int* __restrict__ gid) {
    int f = threadIdx.x & 31;
    int w = threadIdx.x >> 5;
    int node0 = blockIdx.x * 64 + w * 8;
    float acc = 0.0f;
    int cur = -1;
#pragma unroll
    for (int i = 0; i < 8; i++) {
        int n = node0 + i;
        if (n >= N_NODES) break;
        int g = __ldg(&gid[n]);
        if (g != cur) {
            if (cur >= 0) atomicAdd(&g_pool[cur * 32 + f], acc);
            cur = g;
            acc = 0.0f;
        }
        acc += H[(size_t)n * 32 + f];
    }
    if (cur >= 0) atomicAdd(&g_pool[cur * 32 + f], acc);
}

__global__ void count_kernel(const int* __restrict__ gid) {
    int n = blockIdx.x * blockDim.x + threadIdx.x;
    if (n < N_NODES) atomicAdd(&g_cnt[gid[n]], 1.0f);
}

__global__ void classify_kernel(const float* __restrict__ Wc, const float* __restrict__ bc,
                                float* __restrict__ out) {
    int i = threadIdx.x;
    if (i < N_GRAPHS * N_CLASSES) {
        int g = i / N_CLASSES, c = i % N_CLASSES;
        float inv_cnt = 1.0f / fmaxf(g_cnt[g], 1.0f);
        float s = 0.0f;
#pragma unroll
        for (int k = 0; k < 32; k++)
            s += (g_pool[g * 32 + k] * inv_cnt) * Wc[k * N_CLASSES + c];
        out[i] = s + bc[c];
    }
}

// ---------------------------------------------------------------------------
// Launch
// ---------------------------------------------------------------------------
extern "C" void kernel_launch(void* const* d_in, const int* in_sizes, int n_in,
                              void* d_out, int out_size) {
    const float* h   = (const float*)d_in[0];
    const int*   src = (const int*)d_in[1];
    const int*   dst = (const int*)d_in[2];
    const int*   gid = (const int*)d_in[3];
    const float* W[6];
    const float* b[6];
    for (int i = 0; i < 6; i++) {
        W[i] = (const float*)d_in[4 + 2 * i];
        b[i] = (const float*)d_in[5 + 2 * i];
    }
    const float* Wc = (const float*)d_in[16];
    const float* bc = (const float*)d_in[17];
    float* out = (float*)d_out;

    __half *hA, *hB, *wt;
    float* out32;
    cudaGetSymbolAddress((void**)&hA, g_hA);
    cudaGetSymbolAddress((void**)&hB, g_hB);
    cudaGetSymbolAddress((void**)&wt, g_wt);
    cudaGetSymbolAddress((void**)&out32, g_out32);

    const int M = N_NODES;
    const int dims[7] = {512, 1024, 512, 256, 128, 64, 32};
    size_t wt_off[6];
    {
        size_t acc = 0;
        for (int i = 0; i < 6; i++) { wt_off[i] = acc; acc += (size_t)dims[i] * dims[i + 1]; }
    }

    auto smem_bytes = [](int BN) { return 3 * (128 + BN) * 40 * 2; };
    cudaFuncSetAttribute(mma_gemm_kernel<128, true>,  cudaFuncAttributeMaxDynamicSharedMemorySize, smem_bytes(128));
    cudaFuncSetAttribute(mma_gemm_kernel<128, false>, cudaFuncAttributeMaxDynamicSharedMemorySize, smem_bytes(128));
    cudaFuncSetAttribute(mma_gemm_kernel<64,  false>, cudaFuncAttributeMaxDynamicSharedMemorySize, smem_bytes(64));
    cudaFuncSetAttribute(mma_gemm_kernel<32,  false>, cudaFuncAttributeMaxDynamicSharedMemorySize, smem_bytes(32));

    // Graph preprocessing
    init_zero_kernel<<<(N_NODES + 255) / 256, 256>>>();
    degree_kernel<<<(N_EDGES + 255) / 256, 256>>>(src, dst);
    scan_pass1<<<SCAN_BLK, 1024>>>();
    scan_pass2<<<1, 128>>>();
    scan_pass3<<<SCAN_BLK, 1024>>>();
    bin_kernel<<<(N_EDGES + 255) / 256, 256>>>(src, dst);

    // Weight transposes (fp32 -> fp16, [K,N] -> [N,K])
    for (int i = 0; i < 6; i++) {
        int kn = dims[i] * dims[i + 1];
        transpose_kernel<<<(kn + 255) / 256, 256>>>(W[i], wt + wt_off[i], dims[i], dims[i + 1]);
    }

    // Input features fp32 -> fp16
    f2h_kernel<<<(N_NODES * 512 / 4 + 255) / 256, 256>>>(h, hA);

    const int MB = (M + 127) / 128;

    // Layer 1: 512 -> 1024 (SpMM first, then GEMM + bias + relu)
    spmm_kernel<512, false, false><<<(N_NODES + 3) / 4, 256>>>(hA, hB, nullptr);
    mma_gemm_kernel<128, true><<<dim3(1024 / 128, MB), 256, smem_bytes(128)>>>(
        hB, wt + wt_off[0], b[0], hA, M, 512, 1024);

    // Layer 2: 1024 -> 512
    mma_gemm_kernel<128, false><<<dim3(512 / 128, MB), 256, smem_bytes(128)>>>(
        hA, wt + wt_off[1], nullptr, hB, M, 1024, 512);
    spmm_kernel<512, true, false><<<(N_NODES + 3) / 4, 256>>>(hB, hA, b[1]);

    // Layer 3: 512 -> 256
    mma_gemm_kernel<128, false><<<dim3(256 / 128, MB), 256, smem_bytes(128)>>>(
        hA, wt + wt_off[2], nullptr, hB, M, 512, 256);
    spmm_kernel<256, true, false><<<(N_NODES + 7) / 8, 256>>>(hB, hA, b[2]);

    // Layer 4: 256 -> 128
    mma_gemm_kernel<128, false><<<dim3(1, MB), 256, smem_bytes(128)>>>(
        hA, wt + wt_off[3], nullptr, hB, M, 256, 128);
    spmm_kernel<128, true, false><<<(N_NODES + 15) / 16, 256>>>(hB, hA, b[3]);

    // Layer 5: 128 -> 64
    mma_gemm_kernel<64, false><<<dim3(1, MB), 256, smem_bytes(64)>>>(
        hA, wt + wt_off[4], nullptr, hB, M, 128, 64);
    spmm_kernel<64, true, false><<<(N_NODES + 31) / 32, 256>>>(hB, hA, b[4]);

    // Layer 6: 64 -> 32 (SpMM emits fp32 for pooling)
    mma_gemm_kernel<32, false><<<dim3(1, MB), 256, smem_bytes(32)>>>(
        hA, wt + wt_off[5], nullptr, hB, M, 64, 32);
    spmm_kernel<32, true, true><<<(N_NODES + 63) / 64, 256>>>(hB, out32, b[5]);

    // Mean pooling + classifier
    pool_kernel<<<(N_NODES + 63) / 64, 256>>>(out32, gid);
    count_kernel<<<(N_NODES + 255) / 256, 256>>>(gid);
    classify_kernel<<<1, 640>>>(Wc, bc, out);
}

// round 14
// speedup vs baseline: 2.5742x; 1.0052x over previous
#include <cuda_runtime.h>
#include <cuda_fp16.h>
#include <cstddef>
#include <cstdint>

#define N_NODES   100000
#define N_EDGES   3200000
#define N_GRAPHS  64
#define N_CLASSES 10

// ---------------------------------------------------------------------------
// Static device scratch (no allocation allowed)
// ---------------------------------------------------------------------------
__device__ __half g_hA[(size_t)N_NODES * 1024];   // 204.8 MB
__device__ __half g_hB[(size_t)N_NODES * 512];    // 102.4 MB
__device__ float  g_out32[(size_t)N_NODES * 32];  // 12.8 MB (final layer, fp32)
__device__ __half g_wt[1222656];                  // transposed fp16 weights
__device__ int    g_in_deg[N_NODES];
__device__ int    g_out_deg[N_NODES];
__device__ float  g_in_inv[N_NODES];
__device__ float  g_out_inv[N_NODES];
__device__ int    g_row_off[N_NODES + 1];
__device__ int    g_cursor[N_NODES];
__device__ int    g_csr_src[N_EDGES];
__device__ int    g_blocksum[128];
__device__ int    g_blockoff[128];
__device__ float  g_pool[N_GRAPHS * 32];
__device__ float  g_cnt[N_GRAPHS];

// ---------------------------------------------------------------------------
// Helpers (family-portable: cp.async + ldmatrix + mma.sync fp16)
// ---------------------------------------------------------------------------
__device__ __forceinline__ void cp16(uint32_t dst, const void* src, bool valid) {
    asm volatile("cp.async.cg.shared.global [%0], [%1], 16, %2;"
                 :: "r"(dst), "l"(src), "r"(valid ? 16 : 0));
}
#define CP_COMMIT() asm volatile("cp.async.commit_group;" ::: "memory")
#define CP_WAIT(n)  asm volatile("cp.async.wait_group %0;" :: "n"(n) : "memory")

__device__ __forceinline__ void ldsm_x4(uint32_t& r0, uint32_t& r1,
                                        uint32_t& r2, uint32_t& r3, uint32_t addr) {
    asm volatile("ldmatrix.sync.aligned.m8n8.x4.shared.b16 {%0,%1,%2,%3}, [%4];"
                 : "=r"(r0), "=r"(r1), "=r"(r2), "=r"(r3) : "r"(addr));
}

__device__ __forceinline__ void mma_f16(float* d, const uint32_t* a,
                                        uint32_t b0, uint32_t b1) {
    asm volatile(
        "mma.sync.aligned.m16n8k16.row.col.f32.f16.f16.f32 "
        "{%0,%1,%2,%3}, {%4,%5,%6,%7}, {%8,%9}, {%0,%1,%2,%3};"
        : "+f"(d[0]), "+f"(d[1]), "+f"(d[2]), "+f"(d[3])
        : "r"(a[0]), "r"(a[1]), "r"(a[2]), "r"(a[3]), "r"(b0), "r"(b1));
}

// ---------------------------------------------------------------------------
// Preprocessing
// ---------------------------------------------------------------------------
__global__ void init_zero_kernel() {
    int i = blockIdx.x * blockDim.x + threadIdx.x;
    if (i < N_NODES) { g_in_deg[i] = 0; g_out_deg[i] = 0; g_cursor[i] = 0; }
    if (i < N_GRAPHS * 32) g_pool[i] = 0.0f;
    if (i < N_GRAPHS) g_cnt[i] = 0.0f;
}

// degrees + per-graph node counts in one pass
__global__ void degree_kernel(const int* __restrict__ src, const int* __restrict__ dst,
                              const int* __restrict__ gid) {
    int e = blockIdx.x * blockDim.x + threadIdx.x;
    if (e < N_EDGES) {
        atomicAdd(&g_out_deg[src[e]], 1);
        atomicAdd(&g_in_deg[dst[e]], 1);
    }
    if (e < N_NODES) atomicAdd(&g_cnt[gid[e]], 1.0f);
}

#define SCAN_BLK 98
__global__ void scan_pass1() {
    __shared__ int temp[1024];
    int tid = threadIdx.x;
    int i = blockIdx.x * 1024 + tid;
    int v = (i < N_NODES) ? g_in_deg[i] : 0;
    temp[tid] = v;
    __syncthreads();
    for (int off = 1; off < 1024; off <<= 1) {
        int t = (tid >= off) ? temp[tid - off] : 0;
        __syncthreads();
        temp[tid] += t;
        __syncthreads();
    }
    if (i < N_NODES) g_row_off[i] = temp[tid] - v;
    if (tid == 1023) g_blocksum[blockIdx.x] = temp[1023];
}

// parallel prefix over the 98 block sums (each thread sums its own prefix)
__global__ void scan_pass2() {
    __shared__ int s[SCAN_BLK];
    int tid = threadIdx.x;
    if (tid < SCAN_BLK) s[tid] = g_blocksum[tid];
    __syncthreads();
    if (tid < SCAN_BLK) {
        int acc = 0;
        for (int b = 0; b < tid; b++) acc += s[b];
        g_blockoff[tid] = acc;
        if (tid == SCAN_BLK - 1) g_row_off[N_NODES] = acc + s[tid];
    }
}

// pass3 also computes the inverse-sqrt degree scalings
__global__ void scan_pass3() {
    int i = blockIdx.x * 1024 + threadIdx.x;
    if (i < N_NODES) {
        g_row_off[i] += g_blockoff[blockIdx.x];
        g_out_inv[i] = rsqrtf(fmaxf((float)g_out_deg[i], 1.0f));
        g_in_inv[i]  = rsqrtf(fmaxf((float)g_in_deg[i], 1.0f));
    }
}

__global__ void bin_kernel(const int* __restrict__ src, const int* __restrict__ dst) {
    int e = blockIdx.x * blockDim.x + threadIdx.x;
    if (e < N_EDGES) {
        int d = dst[e];
        int pos = g_row_off[d] + atomicAdd(&g_cursor[d], 1);
        g_csr_src[pos] = src[e];
    }
}

// All six W[k][n] (fp32) -> Wt[n][k] (fp16) transposes in ONE kernel.
// Segment boundaries are compile-time constants.
__global__ void transpose_all_kernel(const float* __restrict__ W0, const float* __restrict__ W1,
                                     const float* __restrict__ W2, const float* __restrict__ W3,
                                     const float* __restrict__ W4, const float* __restrict__ W5,
                                     __half* __restrict__ wt) {
    int i = blockIdx.x * blockDim.x + threadIdx.x;
    const float* W; int K, N; int base;
    if (i < 524288)        { W = W0; K = 512;  N = 1024; base = 0; }
    else if (i < 1048576)  { W = W1; K = 1024; N = 512;  base = 524288; }
    else if (i < 1179648)  { W = W2; K = 512;  N = 256;  base = 1048576; }
    else if (i < 1212416)  { W = W3; K = 256;  N = 128;  base = 1179648; }
    else if (i < 1220608)  { W = W4; K = 128;  N = 64;   base = 1212416; }
    else if (i < 1222656)  { W = W5; K = 64;   N = 32;   base = 1220608; }
    else return;
    int local = i - base;
    int k = local / N, n = local % N;
    wt[base + (size_t)n * K + k] = __float2half_rn(W[local]);
}

// fp32 -> fp16 bulk convert (input features)
__global__ void f2h_kernel(const float* __restrict__ x, __half* __restrict__ y) {
    size_t i = ((size_t)blockIdx.x * blockDim.x + threadIdx.x) * 4;
    if (i < (size_t)N_NODES * 512) {
        float4 v = *(const float4*)(x + i);
        __half2* yp = (__half2*)(y + i);
        yp[0] = __floats2half2_rn(v.x, v.y);
        yp[1] = __floats2half2_rn(v.z, v.w);
    }
}

// ---------------------------------------------------------------------------
// SpMM (fp16 gather, fp32 accumulate):
//   Y[n] = in_inv[n] * sum_{s in N(n)} out_inv[s] * X[s]  (+bias, relu)
// 8 halfs per thread (one 16B load per edge); edge loop unrolled x4 for MLP.
// Evict-first output stores keep the gather table X L2-resident.
// ---------------------------------------------------------------------------
template <int D, bool EPI, bool OUT32>
__global__ void spmm_kernel(const __half* __restrict__ X, void* __restrict__ Yv,
                            const float* __restrict__ bias) {
    constexpr int TPN = D / 8;
    constexpr int NPB = 256 / TPN;
    int node = blockIdx.x * NPB + threadIdx.x / TPN;
    if (node >= N_NODES) return;
    int f0 = (threadIdx.x % TPN) * 8;

    float acc[8];
#pragma unroll
    for (int i = 0; i < 8; i++) acc[i] = 0.0f;

    int s0 = g_row_off[node];
    int s1 = g_row_off[node + 1];
    const __half* Xf = X + f0;
    int j = s0;
    for (; j + 4 <= s1; j += 4) {
        int sA = __ldg(&g_csr_src[j]);
        int sB = __ldg(&g_csr_src[j + 1]);
        int sC = __ldg(&g_csr_src[j + 2]);
        int sD = __ldg(&g_csr_src[j + 3]);
        float wA = __ldg(&g_out_inv[sA]);
        float wB = __ldg(&g_out_inv[sB]);
        float wC = __ldg(&g_out_inv[sC]);
        float wD = __ldg(&g_out_inv[sD]);
        float4 pA = *(const float4*)(Xf + (size_t)sA * D);
        float4 pB = *(const float4*)(Xf + (size_t)sB * D);
        float4 pC = *(const float4*)(Xf + (size_t)sC * D);
        float4 pD = *(const float4*)(Xf + (size_t)sD * D);
        const __half2* a2 = (const __half2*)&pA;
        const __half2* b2 = (const __half2*)&pB;
        const __half2* c2 = (const __half2*)&pC;
        const __half2* d2 = (const __half2*)&pD;
#pragma unroll
        for (int i = 0; i < 4; i++) {
            float2 fa = __half22float2(a2[i]);
            float2 fb = __half22float2(b2[i]);
            float2 fc = __half22float2(c2[i]);
            float2 fd = __half22float2(d2[i]);
            acc[2 * i]     += wA * fa.x + wB * fb.x + wC * fc.x + wD * fd.x;
            acc[2 * i + 1] += wA * fa.y + wB * fb.y + wC * fc.y + wD * fd.y;
        }
    }
    for (; j < s1; j++) {
        int s = __ldg(&g_csr_src[j]);
        float w = __ldg(&g_out_inv[s]);
        float4 p = *(const float4*)(Xf + (size_t)s * D);
        const __half2* a2 = (const __half2*)&p;
#pragma unroll
        for (int i = 0; i < 4; i++) {
            float2 fa = __half22float2(a2[i]);
            acc[2 * i]     += w * fa.x;
            acc[2 * i + 1] += w * fa.y;
        }
    }

    float win = g_in_inv[node];
#pragma unroll
    for (int i = 0; i < 8; i++) {
        float v = acc[i] * win;
        if (EPI) v = fmaxf(v + bias[f0 + i], 0.0f);
        acc[i] = v;
    }

    if (OUT32) {
        float* Y = (float*)Yv + (size_t)node * D + f0;
        __stcs((float4*)(Y + 0), make_float4(acc[0], acc[1], acc[2], acc[3]));
        __stcs((float4*)(Y + 4), make_float4(acc[4], acc[5], acc[6], acc[7]));
    } else {
        __half2 o[4];
#pragma unroll
        for (int i = 0; i < 4; i++) o[i] = __floats2half2_rn(acc[2 * i], acc[2 * i + 1]);
        __stcs((float4*)((__half*)Yv + (size_t)node * D + f0), *(float4*)o);
    }
}

// ---------------------------------------------------------------------------
// fp16 mma.sync GEMM: C[M,N] = A[M,K] @ Bt[N,K]^T  (+bias, relu), fp32 accum.
// 128 x BN tile, BK=32 halfs, 256 thr, 3-stage cp.async, ldmatrix frags.
// ---------------------------------------------------------------------------
template <int BN, bool EPI>
__global__ void __launch_bounds__(256)
mma_gemm_kernel(const __half* __restrict__ A, const __half* __restrict__ Bt,
                const float* __restrict__ bias, __half* __restrict__ C,
                int M, int K, int N) {
    extern __shared__ __half smh[];
    constexpr int LD = 40;
    constexpr int A_HALFS = 128 * LD;
    constexpr int B_HALFS = BN * LD;
    constexpr int STAGE = A_HALFS + B_HALFS;
    constexpr int WN = BN / 2;
    constexpr int NT = WN / 8;

    int tid = threadIdx.x;
    int lane = tid & 31, w = tid >> 5;
    int wm = w & 3, wn = w >> 2;
    int gid = lane >> 2, tig = lane & 3;
    int block_m = blockIdx.y * 128;
    int block_n = blockIdx.x * BN;

    uint32_t sm_u32 = (uint32_t)__cvta_generic_to_shared(smh);
    const int nChunks = K >> 5;

    auto load_stage = [&](int c, int buf) {
        int k0 = c << 5;
        uint32_t abase = sm_u32 + buf * STAGE * 2;
        uint32_t bbase = abase + A_HALFS * 2;
#pragma unroll
        for (int t = 0; t < 2; t++) {
            int idx = tid + t * 256;
            int row = idx >> 2, c4 = idx & 3;
            int gm = block_m + row;
            cp16(abase + (row * LD + c4 * 8) * 2,
                 A + (size_t)gm * K + k0 + c4 * 8, gm < M);
        }
#pragma unroll
        for (int t = 0; t < (BN * 4 + 255) / 256; t++) {
            int idx = tid + t * 256;
            if (idx < BN * 4) {
                int row = idx >> 2, c4 = idx & 3;
                cp16(bbase + (row * LD + c4 * 8) * 2,
                     Bt + (size_t)(block_n + row) * K + k0 + c4 * 8, true);
            }
        }
        CP_COMMIT();
    };

    float acc[2][NT][4];
#pragma unroll
    for (int mi = 0; mi < 2; mi++)
#pragma unroll
        for (int ni = 0; ni < NT; ni++)
#pragma unroll
            for (int j = 0; j < 4; j++) acc[mi][ni][j] = 0.0f;

    int a_row = (lane & 7) + ((lane >> 3) & 1) * 8;
    int a_kh  = (lane >> 4) * 8;
    int b_row = (lane & 7) + ((lane >> 4) & 1) * 8;
    int b_kh  = ((lane >> 3) & 1) * 8;

    load_stage(0, 0);
    if (nChunks > 1) load_stage(1, 1);

    for (int c = 0; c < nChunks; c++) {
        if (c + 1 < nChunks) { CP_WAIT(1); } else { CP_WAIT(0); }
        __syncthreads();

        if (c + 2 < nChunks) load_stage(c + 2, (c + 2) % 3);

        int buf = c % 3;
        uint32_t As = sm_u32 + buf * STAGE * 2;
        uint32_t Bs = As + A_HALFS * 2;

#pragma unroll
        for (int kk = 0; kk < 2; kk++) {
            uint32_t af[2][4];
#pragma unroll
            for (int mi = 0; mi < 2; mi++) {
                uint32_t addr = As + (((wm * 32 + mi * 16 + a_row) * LD) + kk * 16 + a_kh) * 2;
                ldsm_x4(af[mi][0], af[mi][1], af[mi][2], af[mi][3], addr);
            }
            uint32_t bf[NT][2];
#pragma unroll
            for (int nj = 0; nj < NT / 2; nj++) {
                uint32_t addr = Bs + (((wn * WN + nj * 16 + b_row) * LD) + kk * 16 + b_kh) * 2;
                ldsm_x4(bf[2 * nj][0], bf[2 * nj][1], bf[2 * nj + 1][0], bf[2 * nj + 1][1], addr);
            }
#pragma unroll
            for (int ni = 0; ni < NT; ni++) {
                mma_f16(acc[0][ni], af[0], bf[ni][0], bf[ni][1]);
                mma_f16(acc[1][ni], af[1], bf[ni][0], bf[ni][1]);
            }
        }
        __syncthreads();
    }

#pragma unroll
    for (int mi = 0; mi < 2; mi++) {
        int gm0 = block_m + wm * 32 + mi * 16 + gid;
#pragma unroll
        for (int ni = 0; ni < NT; ni++) {
            int gn = block_n + wn * WN + ni * 8 + 2 * tig;
            float bx = 0.f, by = 0.f;
            if (EPI) { bx = bias[gn]; by = bias[gn + 1]; }
            if (gm0 < M) {
                float vx = acc[mi][ni][0], vy = acc[mi][ni][1];
                if (EPI) { vx = fmaxf(vx + bx, 0.f); vy = fmaxf(vy + by, 0.f); }
                *(__half2*)(C + (size_t)gm0 * N + gn) = __floats2half2_rn(vx, vy);
            }
            if (gm0 + 8 < M) {
                float vx = acc[mi][ni][2], vy = acc[mi][ni][3];
                if (EPI) { vx = fmaxf(vx + bx, 0.f); vy = fmaxf(vy + by, 0.f); }
                *(__half2*)(C + (size_t)(gm0 + 8) * N + gn) = __floats2half2_rn(vx, vy);
            }
        }
    }
}

// ---------------------------------------------------------------------------
// Pooling + classifier (gid sorted: register-accumulate runs, flush on change)
// ---------------------------------------------------------------------------
__global__ void pool_kernel(const float* __restrict__ H, const int* __restrict__ gid) {
    int f = threadIdx.x & 31;
    int w = threadIdx.x >> 5;
    int node0 = blockIdx.x * 64 + w * 8;
    float acc = 0.0f;
    int cur = -1;
#pragma unroll
    for (int i = 0; i < 8; i++) {
        int n = node0 + i;
        if (n >= N_NODES) break;
        int g = __ldg(&gid[n]);
        if (g != cur) {
            if (cur >= 0) atomicAdd(&g_pool[cur * 32 + f], acc);
            cur = g;
            acc = 0.0f;
        }
        acc += H[(size_t)n * 32 + f];
    }
    if (cur >= 0) atomicAdd(&g_pool[cur * 32 + f], acc);
}

__global__ void classify_kernel(const float* __restrict__ Wc, const float* __restrict__ bc,
                                float* __restrict__ out) {
    int i = threadIdx.x;
    if (i < N_GRAPHS * N_CLASSES) {
        int g = i / N_CLASSES, c = i % N_CLASSES;
        float inv_cnt = 1.0f / fmaxf(g_cnt[g], 1.0f);
        float s = 0.0f;
#pragma unroll
        for (int k = 0; k < 32; k++)
            s += (g_pool[g * 32 + k] * inv_cnt) * Wc[k * N_CLASSES + c];
        out[i] = s + bc[c];
    }
}

// ---------------------------------------------------------------------------
// Launch
// ---------------------------------------------------------------------------
extern "C" void kernel_launch(void* const* d_in, const int* in_sizes, int n_in,
                              void* d_out, int out_size) {
    const float* h   = (const float*)d_in[0];
    const int*   src = (const int*)d_in[1];
    const int*   dst = (const int*)d_in[2];
    const int*   gid = (const int*)d_in[3];
    const float* W[6];
    const float* b[6];
    for (int i = 0; i < 6; i++) {
        W[i] = (const float*)d_in[4 + 2 * i];
        b[i] = (const float*)d_in[5 + 2 * i];
    }
    const float* Wc = (const float*)d_in[16];
    const float* bc = (const float*)d_in[17];
    float* out = (float*)d_out;

    __half *hA, *hB, *wt;
    float* out32;
    cudaGetSymbolAddress((void**)&hA, g_hA);
    cudaGetSymbolAddress((void**)&hB, g_hB);
    cudaGetSymbolAddress((void**)&wt, g_wt);
    cudaGetSymbolAddress((void**)&out32, g_out32);

    const int M = N_NODES;
    size_t wt_off[6] = {0, 524288, 1048576, 1179648, 1212416, 1220608};

    auto smem_bytes = [](int BN) { return 3 * (128 + BN) * 40 * 2; };
    cudaFuncSetAttribute(mma_gemm_kernel<128, true>,  cudaFuncAttributeMaxDynamicSharedMemorySize, smem_bytes(128));
    cudaFuncSetAttribute(mma_gemm_kernel<128, false>, cudaFuncAttributeMaxDynamicSharedMemorySize, smem_bytes(128));
    cudaFuncSetAttribute(mma_gemm_kernel<64,  false>, cudaFuncAttributeMaxDynamicSharedMemorySize, smem_bytes(64));
    cudaFuncSetAttribute(mma_gemm_kernel<32,  false>, cudaFuncAttributeMaxDynamicSharedMemorySize, smem_bytes(32));

    // Graph preprocessing
    init_zero_kernel<<<(N_NODES + 255) / 256, 256>>>();
    degree_kernel<<<(N_EDGES + 255) / 256, 256>>>(src, dst, gid);
    scan_pass1<<<SCAN_BLK, 1024>>>();
    scan_pass2<<<1, 128>>>();
    scan_pass3<<<SCAN_BLK, 1024>>>();
    bin_kernel<<<(N_EDGES + 255) / 256, 256>>>(src, dst);

    // All weight transposes in one launch
    transpose_all_kernel<<<(1222656 + 255) / 256, 256>>>(W[0], W[1], W[2], W[3], W[4], W[5], wt);

    // Input features fp32 -> fp16
    f2h_kernel<<<(N_NODES * 512 / 4 + 255) / 256, 256>>>(h, hA);

    const int MB = (M + 127) / 128;

    // Layer 1: 512 -> 1024 (SpMM first, then GEMM + bias + relu)
    spmm_kernel<512, false, false><<<(N_NODES + 3) / 4, 256>>>(hA, hB, nullptr);
    mma_gemm_kernel<128, true><<<dim3(1024 / 128, MB), 256, smem_bytes(128)>>>(
        hB, wt + wt_off[0], b[0], hA, M, 512, 1024);

    // Layer 2: 1024 -> 512
    mma_gemm_kernel<128, false><<<dim3(512 / 128, MB), 256, smem_bytes(128)>>>(
        hA, wt + wt_off[1], nullptr, hB, M, 1024, 512);
    spmm_kernel<512, true, false><<<(N_NODES + 3) / 4, 256>>>(hB, hA, b[1]);

    // Layer 3: 512 -> 256
    mma_gemm_kernel<128, false><<<dim3(256 / 128, MB), 256, smem_bytes(128)>>>(
        hA, wt + wt_off[2], nullptr, hB, M, 512, 256);
    spmm_kernel<256, true, false><<<(N_NODES + 7) / 8, 256>>>(hB, hA, b[2]);

    // Layer 4: 256 -> 128
    mma_gemm_kernel<128, false><<<dim3(1, MB), 256, smem_bytes(128)>>>(
        hA, wt + wt_off[3], nullptr, hB, M, 256, 128);
    spmm_kernel<128, true, false><<<(N_NODES + 15) / 16, 256>>>(hB, hA, b[3]);

    // Layer 5: 128 -> 64
    mma_gemm_kernel<64, false><<<dim3(1, MB), 256, smem_bytes(64)>>>(
        hA, wt + wt_off[4], nullptr, hB, M, 128, 64);
    spmm_kernel<64, true, false><<<(N_NODES + 31) / 32, 256>>>(hB, hA, b[4]);

    // Layer 6: 64 -> 32 (SpMM emits fp32 for pooling)
    mma_gemm_kernel<32, false><<<dim3(1, MB), 256, smem_bytes(32)>>>(
        hA, wt + wt_off[5], nullptr, hB, M, 64, 32);
    spmm_kernel<32, true, true><<<(N_NODES + 63) / 64, 256>>>(hB, out32, b[5]);

    // Mean pooling + classifier
    pool_kernel<<<(N_NODES + 63) / 64, 256>>>(out32, gid);
    classify_kernel<<<1, 640>>>(Wc, bc, out);
}

// round 15
// speedup vs baseline: 2.6674x; 1.0362x over previous
#include <cuda_runtime.h>
#include <cuda_fp16.h>
#include <cstddef>
#include <cstdint>

#define N_NODES   100000
#define N_EDGES   3200000
#define N_GRAPHS  64
#define N_CLASSES 10

// ---------------------------------------------------------------------------
// Static device scratch (no allocation allowed)
// ---------------------------------------------------------------------------
__device__ __half g_hA[(size_t)N_NODES * 1024];   // 204.8 MB
__device__ __half g_hB[(size_t)N_NODES * 512];    // 102.4 MB
__device__ float  g_out32[(size_t)N_NODES * 32];  // 12.8 MB (final layer, fp32)
__device__ __half g_wt[1222656];                  // transposed fp16 weights
__device__ int    g_in_deg[N_NODES];
__device__ int    g_out_deg[N_NODES];
__device__ float  g_in_inv[N_NODES];
__device__ float  g_out_inv[N_NODES];
__device__ int    g_row_off[N_NODES + 1];
__device__ int    g_cursor[N_NODES];
__device__ int    g_csr_src[N_EDGES];
__device__ int    g_blocksum[128];
__device__ int    g_blockoff[128];
__device__ float  g_pool[N_GRAPHS * 32];
__device__ float  g_cnt[N_GRAPHS];

// ---------------------------------------------------------------------------
// Helpers (family-portable: cp.async + ldmatrix + mma.sync fp16)
// ---------------------------------------------------------------------------
__device__ __forceinline__ void cp16(uint32_t dst, const void* src, bool valid) {
    asm volatile("cp.async.cg.shared.global [%0], [%1], 16, %2;"
                 :: "r"(dst), "l"(src), "r"(valid ? 16 : 0));
}
#define CP_COMMIT() asm volatile("cp.async.commit_group;" ::: "memory")
#define CP_WAIT(n)  asm volatile("cp.async.wait_group %0;" :: "n"(n) : "memory")

__device__ __forceinline__ void ldsm_x4(uint32_t& r0, uint32_t& r1,
                                        uint32_t& r2, uint32_t& r3, uint32_t addr) {
    asm volatile("ldmatrix.sync.aligned.m8n8.x4.shared.b16 {%0,%1,%2,%3}, [%4];"
                 : "=r"(r0), "=r"(r1), "=r"(r2), "=r"(r3) : "r"(addr));
}

__device__ __forceinline__ void mma_f16(float* d, const uint32_t* a,
                                        uint32_t b0, uint32_t b1) {
    asm volatile(
        "mma.sync.aligned.m16n8k16.row.col.f32.f16.f16.f32 "
        "{%0,%1,%2,%3}, {%4,%5,%6,%7}, {%8,%9}, {%0,%1,%2,%3};"
        : "+f"(d[0]), "+f"(d[1]), "+f"(d[2]), "+f"(d[3])
        : "r"(a[0]), "r"(a[1]), "r"(a[2]), "r"(a[3]), "r"(b0), "r"(b1));
}

// ---------------------------------------------------------------------------
// Preprocessing
// ---------------------------------------------------------------------------
__global__ void init_zero_kernel() {
    int i = blockIdx.x * blockDim.x + threadIdx.x;
    if (i < N_NODES) { g_in_deg[i] = 0; g_out_deg[i] = 0; g_cursor[i] = 0; }
    if (i < N_GRAPHS * 32) g_pool[i] = 0.0f;
    if (i < N_GRAPHS) g_cnt[i] = 0.0f;
}

// One grid-segmented kernel: f2h convert + degree/count atomics + weight
// transposes — all mutually independent; overlaps streaming and atomic work.
#define F_BLK 50000   // 100000*512/4 / 256
#define E_BLK 12500   // 3200000 / 256
#define T_BLK 4776    // ceil(1222656 / 256)
__global__ void prep_kernel(const int* __restrict__ src, const int* __restrict__ dst,
                            const int* __restrict__ gid,
                            const float* __restrict__ h, __half* __restrict__ hA,
                            const float* __restrict__ W0, const float* __restrict__ W1,
                            const float* __restrict__ W2, const float* __restrict__ W3,
                            const float* __restrict__ W4, const float* __restrict__ W5,
                            __half* __restrict__ wt) {
    int b = blockIdx.x;
    if (b < F_BLK) {
        size_t i = ((size_t)b * 256 + threadIdx.x) * 4;
        float4 v = *(const float4*)(h + i);
        __half2* yp = (__half2*)(hA + i);
        yp[0] = __floats2half2_rn(v.x, v.y);
        yp[1] = __floats2half2_rn(v.z, v.w);
    } else if (b < F_BLK + E_BLK) {
        int e = (b - F_BLK) * 256 + threadIdx.x;
        atomicAdd(&g_out_deg[src[e]], 1);
        atomicAdd(&g_in_deg[dst[e]], 1);
        if (e < N_NODES) atomicAdd(&g_cnt[gid[e]], 1.0f);
    } else {
        int i = (b - F_BLK - E_BLK) * 256 + threadIdx.x;
        const float* W; int N; int base;
        if (i < 524288)        { W = W0; N = 1024; base = 0; }
        else if (i < 1048576)  { W = W1; N = 512;  base = 524288; }
        else if (i < 1179648)  { W = W2; N = 256;  base = 1048576; }
        else if (i < 1212416)  { W = W3; N = 128;  base = 1179648; }
        else if (i < 1220608)  { W = W4; N = 64;   base = 1212416; }
        else if (i < 1222656)  { W = W5; N = 32;   base = 1220608; }
        else return;
        int local = i - base;
        int K = (base == 0) ? 512 : (base == 524288 ? 1024 : (base == 1048576 ? 512 :
                 (base == 1179648 ? 256 : (base == 1212416 ? 128 : 64))));
        int k = local / N, n = local % N;
        wt[base + (size_t)n * K + k] = __float2half_rn(W[local]);
    }
}

#define SCAN_BLK 98
__global__ void scan_pass1() {
    __shared__ int temp[1024];
    int tid = threadIdx.x;
    int i = blockIdx.x * 1024 + tid;
    int v = (i < N_NODES) ? g_in_deg[i] : 0;
    temp[tid] = v;
    __syncthreads();
    for (int off = 1; off < 1024; off <<= 1) {
        int t = (tid >= off) ? temp[tid - off] : 0;
        __syncthreads();
        temp[tid] += t;
        __syncthreads();
    }
    if (i < N_NODES) g_row_off[i] = temp[tid] - v;
    if (tid == 1023) g_blocksum[blockIdx.x] = temp[1023];
}

__global__ void scan_pass2() {
    __shared__ int s[SCAN_BLK];
    int tid = threadIdx.x;
    if (tid < SCAN_BLK) s[tid] = g_blocksum[tid];
    __syncthreads();
    if (tid < SCAN_BLK) {
        int acc = 0;
        for (int b = 0; b < tid; b++) acc += s[b];
        g_blockoff[tid] = acc;
        if (tid == SCAN_BLK - 1) g_row_off[N_NODES] = acc + s[tid];
    }
}

__global__ void scan_pass3() {
    int i = blockIdx.x * 1024 + threadIdx.x;
    if (i < N_NODES) {
        g_row_off[i] += g_blockoff[blockIdx.x];
        g_out_inv[i] = rsqrtf(fmaxf((float)g_out_deg[i], 1.0f));
        g_in_inv[i]  = rsqrtf(fmaxf((float)g_in_deg[i], 1.0f));
    }
}

__global__ void bin_kernel(const int* __restrict__ src, const int* __restrict__ dst) {
    int e = blockIdx.x * blockDim.x + threadIdx.x;
    if (e < N_EDGES) {
        int d = dst[e];
        int pos = g_row_off[d] + atomicAdd(&g_cursor[d], 1);
        g_csr_src[pos] = src[e];
    }
}

// ---------------------------------------------------------------------------
// SpMM edge-loop body (shared by both variants): 8 halfs / thread / edge.
// ---------------------------------------------------------------------------
__device__ __forceinline__ void spmm_edges(float* acc, const __half* Xf, int D,
                                           int s0, int s1) {
    int j = s0;
    for (; j + 4 <= s1; j += 4) {
        int sA = __ldg(&g_csr_src[j]);
        int sB = __ldg(&g_csr_src[j + 1]);
        int sC = __ldg(&g_csr_src[j + 2]);
        int sD = __ldg(&g_csr_src[j + 3]);
        float wA = __ldg(&g_out_inv[sA]);
        float wB = __ldg(&g_out_inv[sB]);
        float wC = __ldg(&g_out_inv[sC]);
        float wD = __ldg(&g_out_inv[sD]);
        float4 pA = *(const float4*)(Xf + (size_t)sA * D);
        float4 pB = *(const float4*)(Xf + (size_t)sB * D);
        float4 pC = *(const float4*)(Xf + (size_t)sC * D);
        float4 pD = *(const float4*)(Xf + (size_t)sD * D);
        const __half2* a2 = (const __half2*)&pA;
        const __half2* b2 = (const __half2*)&pB;
        const __half2* c2 = (const __half2*)&pC;
        const __half2* d2 = (const __half2*)&pD;
#pragma unroll
        for (int i = 0; i < 4; i++) {
            float2 fa = __half22float2(a2[i]);
            float2 fb = __half22float2(b2[i]);
            float2 fc = __half22float2(c2[i]);
            float2 fd = __half22float2(d2[i]);
            acc[2 * i]     += wA * fa.x + wB * fb.x + wC * fc.x + wD * fd.x;
            acc[2 * i + 1] += wA * fa.y + wB * fb.y + wC * fc.y + wD * fd.y;
        }
    }
    for (; j < s1; j++) {
        int s = __ldg(&g_csr_src[j]);
        float w = __ldg(&g_out_inv[s]);
        float4 p = *(const float4*)(Xf + (size_t)s * D);
        const __half2* a2 = (const __half2*)&p;
#pragma unroll
        for (int i = 0; i < 4; i++) {
            float2 fa = __half22float2(a2[i]);
            acc[2 * i]     += w * fa.x;
            acc[2 * i + 1] += w * fa.y;
        }
    }
}

// ---------------------------------------------------------------------------
// Chunked D=512 SpMM: two 256-feature passes, each with a 51 MB (L2-resident)
// gather table. chunk = blockIdx.x / 12500 so pass 0 drains before pass 1.
// Same 16B-per-thread unrolled loop as the proven flat kernel.
// ---------------------------------------------------------------------------
template <bool EPI>
__global__ void spmm512_kernel(const __half* __restrict__ X, __half* __restrict__ Y,
                               const float* __restrict__ bias) {
    constexpr int D = 512, TPN = 32, NPB = 8, NBLK = 12500;
    int chunk = blockIdx.x / NBLK;
    int blk   = blockIdx.x % NBLK;
    int node = blk * NPB + threadIdx.x / TPN;
    int f0 = chunk * 256 + (threadIdx.x % TPN) * 8;

    float acc[8];
#pragma unroll
    for (int i = 0; i < 8; i++) acc[i] = 0.0f;

    spmm_edges(acc, X + f0, D, g_row_off[node], g_row_off[node + 1]);

    float win = g_in_inv[node];
    __half2 o[4];
#pragma unroll
    for (int i = 0; i < 4; i++) {
        float vx = acc[2 * i] * win;
        float vy = acc[2 * i + 1] * win;
        if (EPI) {
            vx = fmaxf(vx + bias[f0 + 2 * i], 0.0f);
            vy = fmaxf(vy + bias[f0 + 2 * i + 1], 0.0f);
        }
        o[i] = __floats2half2_rn(vx, vy);
    }
    __stcs((float4*)(Y + (size_t)node * D + f0), *(float4*)o);
}

// ---------------------------------------------------------------------------
// Flat SpMM for D <= 256 (and fp32 output for the final layer)
// ---------------------------------------------------------------------------
template <int D, bool EPI, bool OUT32>
__global__ void spmm_kernel(const __half* __restrict__ X, void* __restrict__ Yv,
                            const float* __restrict__ bias) {
    constexpr int TPN = D / 8;
    constexpr int NPB = 256 / TPN;
    int node = blockIdx.x * NPB + threadIdx.x / TPN;
    if (node >= N_NODES) return;
    int f0 = (threadIdx.x % TPN) * 8;

    float acc[8];
#pragma unroll
    for (int i = 0; i < 8; i++) acc[i] = 0.0f;

    spmm_edges(acc, X + f0, D, g_row_off[node], g_row_off[node + 1]);

    float win = g_in_inv[node];
#pragma unroll
    for (int i = 0; i < 8; i++) {
        float v = acc[i] * win;
        if (EPI) v = fmaxf(v + bias[f0 + i], 0.0f);
        acc[i] = v;
    }

    if (OUT32) {
        float* Y = (float*)Yv + (size_t)node * D + f0;
        __stcs((float4*)(Y + 0), make_float4(acc[0], acc[1], acc[2], acc[3]));
        __stcs((float4*)(Y + 4), make_float4(acc[4], acc[5], acc[6], acc[7]));
    } else {
        __half2 o[4];
#pragma unroll
        for (int i = 0; i < 4; i++) o[i] = __floats2half2_rn(acc[2 * i], acc[2 * i + 1]);
        __stcs((float4*)((__half*)Yv + (size_t)node * D + f0), *(float4*)o);
    }
}

// ---------------------------------------------------------------------------
// fp16 mma.sync GEMM: C[M,N] = A[M,K] @ Bt[N,K]^T  (+bias, relu), fp32 accum.
// 128 x BN tile, BK=32 halfs, 256 thr, 3-stage cp.async, ldmatrix frags.
// ---------------------------------------------------------------------------
template <int BN, bool EPI>
__global__ void __launch_bounds__(256)
mma_gemm_kernel(const __half* __restrict__ A, const __half* __restrict__ Bt,
                const float* __restrict__ bias, __half* __restrict__ C,
                int M, int K, int N) {
    extern __shared__ __half smh[];
    constexpr int LD = 40;
    constexpr int A_HALFS = 128 * LD;
    constexpr int B_HALFS = BN * LD;
    constexpr int STAGE = A_HALFS + B_HALFS;
    constexpr int WN = BN / 2;
    constexpr int NT = WN / 8;

    int tid = threadIdx.x;
    int lane = tid & 31, w = tid >> 5;
    int wm = w & 3, wn = w >> 2;
    int gid = lane >> 2, tig = lane & 3;
    int block_m = blockIdx.y * 128;
    int block_n = blockIdx.x * BN;

    uint32_t sm_u32 = (uint32_t)__cvta_generic_to_shared(smh);
    const int nChunks = K >> 5;

    auto load_stage = [&](int c, int buf) {
        int k0 = c << 5;
        uint32_t abase = sm_u32 + buf * STAGE * 2;
        uint32_t bbase = abase + A_HALFS * 2;
#pragma unroll
        for (int t = 0; t < 2; t++) {
            int idx = tid + t * 256;
            int row = idx >> 2, c4 = idx & 3;
            int gm = block_m + row;
            cp16(abase + (row * LD + c4 * 8) * 2,
                 A + (size_t)gm * K + k0 + c4 * 8, gm < M);
        }
#pragma unroll
        for (int t = 0; t < (BN * 4 + 255) / 256; t++) {
            int idx = tid + t * 256;
            if (idx < BN * 4) {
                int row = idx >> 2, c4 = idx & 3;
                cp16(bbase + (row * LD + c4 * 8) * 2,
                     Bt + (size_t)(block_n + row) * K + k0 + c4 * 8, true);
            }
        }
        CP_COMMIT();
    };

    float acc[2][NT][4];
#pragma unroll
    for (int mi = 0; mi < 2; mi++)
#pragma unroll
        for (int ni = 0; ni < NT; ni++)
#pragma unroll
            for (int j = 0; j < 4; j++) acc[mi][ni][j] = 0.0f;

    int a_row = (lane & 7) + ((lane >> 3) & 1) * 8;
    int a_kh  = (lane >> 4) * 8;
    int b_row = (lane & 7) + ((lane >> 4) & 1) * 8;
    int b_kh  = ((lane >> 3) & 1) * 8;

    load_stage(0, 0);
    if (nChunks > 1) load_stage(1, 1);

    for (int c = 0; c < nChunks; c++) {
        if (c + 1 < nChunks) { CP_WAIT(1); } else { CP_WAIT(0); }
        __syncthreads();

        if (c + 2 < nChunks) load_stage(c + 2, (c + 2) % 3);

        int buf = c % 3;
        uint32_t As = sm_u32 + buf * STAGE * 2;
        uint32_t Bs = As + A_HALFS * 2;

#pragma unroll
        for (int kk = 0; kk < 2; kk++) {
            uint32_t af[2][4];
#pragma unroll
            for (int mi = 0; mi < 2; mi++) {
                uint32_t addr = As + (((wm * 32 + mi * 16 + a_row) * LD) + kk * 16 + a_kh) * 2;
                ldsm_x4(af[mi][0], af[mi][1], af[mi][2], af[mi][3], addr);
            }
            uint32_t bf[NT][2];
#pragma unroll
            for (int nj = 0; nj < NT / 2; nj++) {
                uint32_t addr = Bs + (((wn * WN + nj * 16 + b_row) * LD) + kk * 16 + b_kh) * 2;
                ldsm_x4(bf[2 * nj][0], bf[2 * nj][1], bf[2 * nj + 1][0], bf[2 * nj + 1][1], addr);
            }
#pragma unroll
            for (int ni = 0; ni < NT; ni++) {
                mma_f16(acc[0][ni], af[0], bf[ni][0], bf[ni][1]);
                mma_f16(acc[1][ni], af[1], bf[ni][0], bf[ni][1]);
            }
        }
        __syncthreads();
    }

#pragma unroll
    for (int mi = 0; mi < 2; mi++) {
        int gm0 = block_m + wm * 32 + mi * 16 + gid;
#pragma unroll
        for (int ni = 0; ni < NT; ni++) {
            int gn = block_n + wn * WN + ni * 8 + 2 * tig;
            float bx = 0.f, by = 0.f;
            if (EPI) { bx = bias[gn]; by = bias[gn + 1]; }
            if (gm0 < M) {
                float vx = acc[mi][ni][0], vy = acc[mi][ni][1];
                if (EPI) { vx = fmaxf(vx + bx, 0.f); vy = fmaxf(vy + by, 0.f); }
                *(__half2*)(C + (size_t)gm0 * N + gn) = __floats2half2_rn(vx, vy);
            }
            if (gm0 + 8 < M) {
                float vx = acc[mi][ni][2], vy = acc[mi][ni][3];
                if (EPI) { vx = fmaxf(vx + bx, 0.f); vy = fmaxf(vy + by, 0.f); }
                *(__half2*)(C + (size_t)(gm0 + 8) * N + gn) = __floats2half2_rn(vx, vy);
            }
        }
    }
}

// ---------------------------------------------------------------------------
// Pooling + classifier (gid sorted: register-accumulate runs, flush on change)
// ---------------------------------------------------------------------------
__global__ void pool_kernel(const float* __restrict__ H, const int* __restrict__ gid) {
    int f = threadIdx.x & 31;
    int w = threadIdx.x >> 5;
    int node0 = blockIdx.x * 64 + w * 8;
    float acc = 0.0f;
    int cur = -1;
#pragma unroll
    for (int i = 0; i < 8; i++) {
        int n = node0 + i;
        if (n >= N_NODES) break;
        int g = __ldg(&gid[n]);
        if (g != cur) {
            if (cur >= 0) atomicAdd(&g_pool[cur * 32 + f], acc);
            cur = g;
            acc = 0.0f;
        }
        acc += H[(size_t)n * 32 + f];
    }
    if (cur >= 0) atomicAdd(&g_pool[cur * 32 + f], acc);
}

__global__ void classify_kernel(const float* __restrict__ Wc, const float* __restrict__ bc,
                                float* __restrict__ out) {
    int i = threadIdx.x;
    if (i < N_GRAPHS * N_CLASSES) {
        int g = i / N_CLASSES, c = i % N_CLASSES;
        float inv_cnt = 1.0f / fmaxf(g_cnt[g], 1.0f);
        float s = 0.0f;
#pragma unroll
        for (int k = 0; k < 32; k++)
            s += (g_pool[g * 32 + k] * inv_cnt) * Wc[k * N_CLASSES + c];
        out[i] = s + bc[c];
    }
}

// ---------------------------------------------------------------------------
// Launch
// ---------------------------------------------------------------------------
extern "C" void kernel_launch(void* const* d_in, const int* in_sizes, int n_in,
                              void* d_out, int out_size) {
    const float* h   = (const float*)d_in[0];
    const int*   src = (const int*)d_in[1];
    const int*   dst = (const int*)d_in[2];
    const int*   gid = (const int*)d_in[3];
    const float* W[6];
    const float* b[6];
    for (int i = 0; i < 6; i++) {
        W[i] = (const float*)d_in[4 + 2 * i];
        b[i] = (const float*)d_in[5 + 2 * i];
    }
    const float* Wc = (const float*)d_in[16];
    const float* bc = (const float*)d_in[17];
    float* out = (float*)d_out;

    __half *hA, *hB, *wt;
    float* out32;
    cudaGetSymbolAddress((void**)&hA, g_hA);
    cudaGetSymbolAddress((void**)&hB, g_hB);
    cudaGetSymbolAddress((void**)&wt, g_wt);
    cudaGetSymbolAddress((void**)&out32, g_out32);

    const int M = N_NODES;
    size_t wt_off[6] = {0, 524288, 1048576, 1179648, 1212416, 1220608};

    auto smem_bytes = [](int BN) { return 3 * (128 + BN) * 40 * 2; };
    cudaFuncSetAttribute(mma_gemm_kernel<128, true>,  cudaFuncAttributeMaxDynamicSharedMemorySize, smem_bytes(128));
    cudaFuncSetAttribute(mma_gemm_kernel<128, false>, cudaFuncAttributeMaxDynamicSharedMemorySize, smem_bytes(128));
    cudaFuncSetAttribute(mma_gemm_kernel<64,  false>, cudaFuncAttributeMaxDynamicSharedMemorySize, smem_bytes(64));
    cudaFuncSetAttribute(mma_gemm_kernel<32,  false>, cudaFuncAttributeMaxDynamicSharedMemorySize, smem_bytes(32));

    // Graph preprocessing: init, then fused (f2h | degrees+counts | transposes)
    init_zero_kernel<<<(N_NODES + 255) / 256, 256>>>();
    prep_kernel<<<F_BLK + E_BLK + T_BLK, 256>>>(src, dst, gid, h, hA,
                                                W[0], W[1], W[2], W[3], W[4], W[5], wt);
    scan_pass1<<<SCAN_BLK, 1024>>>();
    scan_pass2<<<1, 128>>>();
    scan_pass3<<<SCAN_BLK, 1024>>>();
    bin_kernel<<<(N_EDGES + 255) / 256, 256>>>(src, dst);

    const int MB = (M + 127) / 128;

    // Layer 1: 512 -> 1024 (chunked SpMM, then GEMM + bias + relu)
    spmm512_kernel<false><<<25000, 256>>>(hA, hB, nullptr);
    mma_gemm_kernel<128, true><<<dim3(1024 / 128, MB), 256, smem_bytes(128)>>>(
        hB, wt + wt_off[0], b[0], hA, M, 512, 1024);

    // Layer 2: 1024 -> 512 (GEMM, then chunked SpMM + bias + relu)
    mma_gemm_kernel<128, false><<<dim3(512 / 128, MB), 256, smem_bytes(128)>>>(
        hA, wt + wt_off[1], nullptr, hB, M, 1024, 512);
    spmm512_kernel<true><<<25000, 256>>>(hB, hA, b[1]);

    // Layer 3: 512 -> 256
    mma_gemm_kernel<128, false><<<dim3(256 / 128, MB), 256, smem_bytes(128)>>>(
        hA, wt + wt_off[2], nullptr, hB, M, 512, 256);
    spmm_kernel<256, true, false><<<(N_NODES + 7) / 8, 256>>>(hB, hA, b[2]);

    // Layer 4: 256 -> 128
    mma_gemm_kernel<128, false><<<dim3(1, MB), 256, smem_bytes(128)>>>(
        hA, wt + wt_off[3], nullptr, hB, M, 256, 128);
    spmm_kernel<128, true, false><<<(N_NODES + 15) / 16, 256>>>(hB, hA, b[3]);

    // Layer 5: 128 -> 64
    mma_gemm_kernel<64, false><<<dim3(1, MB), 256, smem_bytes(64)>>>(
        hA, wt + wt_off[4], nullptr, hB, M, 128, 64);
    spmm_kernel<64, true, false><<<(N_NODES + 31) / 32, 256>>>(hB, hA, b[4]);

    // Layer 6: 64 -> 32 (SpMM emits fp32 for pooling)
    mma_gemm_kernel<32, false><<<dim3(1, MB), 256, smem_bytes(32)>>>(
        hA, wt + wt_off[5], nullptr, hB, M, 64, 32);
    spmm_kernel<32, true, true><<<(N_NODES + 63) / 64, 256>>>(hB, out32, b[5]);

    // Mean pooling + classifier
    pool_kernel<<<(N_NODES + 63) / 64, 256>>>(out32, gid);
    classify_kernel<<<1, 640>>>(Wc, bc, out);
}